// round 9
// baseline (speedup 1.0000x reference)
#include <cuda_runtime.h>
#include <math.h>

#define NPC 16384
#define NTC 131072
#define NFC 131072
#define EC  262144
#define BC  256
#define FULLMASK 0xffffffffu

// ---------------- device scratch ----------------
__device__ float g_xp[NPC * 64];
__device__ float g_xt[NTC * 64];        // single-buffered: gat_p reads before agg_tf overwrites
__device__ float g_xf[NFC * 64];
__device__ float g_ap[NPC * 64];
__device__ float g_hs0[NPC * 64];       // xp @ W[pt]
__device__ float g_hs1[NPC * 64];       // xp @ W[pf]
__device__ float g_ss_pt[2][NPC], g_ss_pf[2][NPC], g_sd_tp[2][NPC], g_sd_fp[2][NPC];
__device__ float g_ss_tp[2][NTC], g_sd_pt[2][NTC];
__device__ float g_ss_fp[2][NFC], g_sd_pf[2][NFC];
__device__ float g_wsv[5 * 4 * 64], g_wdv[5 * 4 * 64];
__device__ int g_rp_pt[NTC + 1], g_rp_pf[NFC + 1];
__device__ int g_rp_tp[NPC + 1], g_rp_fp[NPC + 1];
__device__ int g_cs_pt[EC], g_cs_tp[EC], g_cs_pf[EC], g_cs_fp[EC];
__device__ int g_cnt[4 * NTC];
__device__ float g_ra[NPC * 2];
__device__ float g_rep[BC * 576];
__device__ float g_h1[BC * 64], g_h2[BC * 64];

// ---------------- batched CSR build ----------------
__global__ void zero4(int* c) {
    int i = blockIdx.x * blockDim.x + threadIdx.x;
    if (i < 4 * NTC) c[i] = 0;
}

__global__ void hist4(const int* __restrict__ d0, const int* __restrict__ d1,
                      const int* __restrict__ d2, const int* __restrict__ d3,
                      int* __restrict__ cnt) {
    int t = blockIdx.y;
    const int* d = (t == 0) ? d0 : (t == 1) ? d1 : (t == 2) ? d2 : d3;
    int* c = cnt + t * NTC;
    int i = blockIdx.x * blockDim.x + threadIdx.x;
    if (i < EC) atomicAdd(&c[d[i]], 1);
}

__device__ void scan_body(const int* __restrict__ deg, int* __restrict__ rowptr,
                          int* __restrict__ rezero, int n) {
    __shared__ int warp_sums[32];
    __shared__ int s_carry;
    int tid = threadIdx.x;
    int lane = tid & 31, wid = tid >> 5;
    if (tid == 0) s_carry = 0;
    __syncthreads();
    for (int base = 0; base < n; base += 1024) {
        int i = base + tid;
        int v = (i < n) ? deg[i] : 0;
        int x = v;
        #pragma unroll
        for (int off = 1; off < 32; off <<= 1) {
            int y = __shfl_up_sync(FULLMASK, x, off);
            if (lane >= off) x += y;
        }
        if (lane == 31) warp_sums[wid] = x;
        __syncthreads();
        if (tid < 32) {
            int s = warp_sums[tid];
            #pragma unroll
            for (int off = 1; off < 32; off <<= 1) {
                int y = __shfl_up_sync(FULLMASK, s, off);
                if (tid >= off) s += y;
            }
            warp_sums[tid] = s;
        }
        __syncthreads();
        int incl = x + (wid ? warp_sums[wid - 1] : 0);
        if (i < n) { rowptr[i] = s_carry + incl - v; rezero[i] = 0; }
        int chunk_total = warp_sums[31];
        __syncthreads();
        if (tid == 0) s_carry += chunk_total;
        __syncthreads();
    }
    if (tid == 0) rowptr[n] = s_carry;
}

__global__ void scan4(int* __restrict__ cnt,
                      int* rp0, int* rp1, int* rp2, int* rp3) {
    int t = blockIdx.x;
    int* rp = (t == 0) ? rp0 : (t == 1) ? rp1 : (t == 2) ? rp2 : rp3;
    int n = (t == 0) ? NTC : (t == 1) ? NPC : (t == 2) ? NFC : NPC;
    scan_body(cnt + t * NTC, rp, cnt + t * NTC, n);
}

__global__ void scatter4(const int* __restrict__ s0, const int* __restrict__ d0,
                         const int* __restrict__ s1, const int* __restrict__ d1,
                         const int* __restrict__ s2, const int* __restrict__ d2,
                         const int* __restrict__ s3, const int* __restrict__ d3,
                         const int* rp0, const int* rp1, const int* rp2, const int* rp3,
                         int* __restrict__ cnt,
                         int* c0, int* c1, int* c2, int* c3) {
    int t = blockIdx.y;
    const int* src = (t == 0) ? s0 : (t == 1) ? s1 : (t == 2) ? s2 : s3;
    const int* dst = (t == 0) ? d0 : (t == 1) ? d1 : (t == 2) ? d2 : d3;
    const int* rp  = (t == 0) ? rp0 : (t == 1) ? rp1 : (t == 2) ? rp2 : rp3;
    int* csr = (t == 0) ? c0 : (t == 1) ? c1 : (t == 2) ? c2 : c3;
    int* cur = cnt + t * NTC;
    int i = blockIdx.x * blockDim.x + threadIdx.x;
    if (i >= EC) return;
    int d = dst[i];
    int pos = rp[d] + atomicAdd(&cur[d], 1);
    csr[pos] = src[i];
}

// ---------------- score vectors for ALL layers ----------------
__global__ void vec_all(const float* __restrict__ Ws, const float* __restrict__ as,
                        const float* __restrict__ Wd, const float* __restrict__ ad,
                        float* __restrict__ wsv, float* __restrict__ wdv) {
    int idx = blockIdx.x * blockDim.x + threadIdx.x;
    if (idx >= 2 * 5 * 4 * 64) return;
    int which = idx >= 1280;
    int r = which ? idx - 1280 : idx;
    int i = r & 63, lt = r >> 6;
    const float* W = which ? Wd : Ws;
    const float* a = which ? ad : as;
    float* o = which ? wdv : wsv;
    float acc = 0.f;
    const float* wr = W + (size_t)(lt * 64 + i) * 64;
    const float* ar = a + lt * 64;
    #pragma unroll 8
    for (int j = 0; j < 64; j++) acc = fmaf(wr[j], ar[j], acc);
    o[r] = acc;
}

// ---------------- embed ----------------
__global__ void embed_k(const float* __restrict__ mass, const int* __restrict__ pstate,
                        const float* __restrict__ embW, const float* __restrict__ embS,
                        float* __restrict__ xp) {
    int idx = blockIdx.x * blockDim.x + threadIdx.x;
    if (idx >= NPC * 64) return;
    int n = idx >> 6, j = idx & 63;
    float v;
    if (j < 32) v = mass[n] * embW[j];
    else {
        int st = pstate[2 * n] + 2 * pstate[2 * n + 1];
        v = embS[st * 32 + (j - 32)];
    }
    xp[idx] = v;
}

// ---------------- up to 4 per-row dot products (layer-0 init) ----------------
__global__ void dot4(const float* __restrict__ X, int n,
                     const float* v0, float* o0, const float* v1, float* o1,
                     const float* v2, float* o2, const float* v3, float* o3) {
    int idx = blockIdx.x * blockDim.x + threadIdx.x;
    int w = idx >> 5;
    if (w >= n) return;
    int lane = idx & 31;
    float2 x = *(const float2*)&X[(size_t)w * 64 + lane * 2];
#define DODOT(v, o) if (v) { \
        float s = x.x * v[2 * lane] + x.y * v[2 * lane + 1]; \
        for (int off = 16; off; off >>= 1) s += __shfl_xor_sync(FULLMASK, s, off); \
        if (lane == 0) o[w] = s; }
    DODOT(v0, o0)
    DODOT(v1, o1)
    DODOT(v2, o2)
    DODOT(v3, o3)
#undef DODOT
}

// ---------------- hs matmul: hs0 = X@W0, hs1 = X@W1 (blockIdx split) ----------------
__global__ void __launch_bounds__(256) mm_hs(const float* __restrict__ X,
                                             const float* __restrict__ W0, float* __restrict__ Y0,
                                             const float* __restrict__ W1, float* __restrict__ Y1) {
    __shared__ float Xs[64][65];
    __shared__ float Wsh[64][68];
    int half = blockIdx.x >= (NPC / 64);
    int row0 = (half ? blockIdx.x - NPC / 64 : blockIdx.x) * 64;
    const float* W = half ? W1 : W0;
    float* Y = half ? Y1 : Y0;
    int tid = threadIdx.x;
    const float4* W4 = (const float4*)W;
    for (int i = tid; i < 1024; i += 256) {
        float4 v = W4[i];
        int r = i >> 4, c = (i & 15) * 4;
        Wsh[r][c] = v.x; Wsh[r][c + 1] = v.y; Wsh[r][c + 2] = v.z; Wsh[r][c + 3] = v.w;
    }
    const float4* X4 = (const float4*)(X + (size_t)row0 * 64);
    for (int i = tid; i < 1024; i += 256) {
        float4 v = X4[i];
        int r = i >> 4, c = (i & 15) * 4;
        Xs[r][c] = v.x; Xs[r][c + 1] = v.y; Xs[r][c + 2] = v.z; Xs[r][c + 3] = v.w;
    }
    __syncthreads();
    int tx = tid & 15, ty = tid >> 4;
    int c0 = tx * 4, r0 = ty * 4;
    float acc[4][4] = {};
    #pragma unroll
    for (int k = 0; k < 64; k++) {
        float4 w = *(const float4*)&Wsh[k][c0];
        float x0 = Xs[r0][k], x1 = Xs[r0 + 1][k], x2 = Xs[r0 + 2][k], x3 = Xs[r0 + 3][k];
        acc[0][0] = fmaf(x0, w.x, acc[0][0]); acc[0][1] = fmaf(x0, w.y, acc[0][1]);
        acc[0][2] = fmaf(x0, w.z, acc[0][2]); acc[0][3] = fmaf(x0, w.w, acc[0][3]);
        acc[1][0] = fmaf(x1, w.x, acc[1][0]); acc[1][1] = fmaf(x1, w.y, acc[1][1]);
        acc[1][2] = fmaf(x1, w.z, acc[1][2]); acc[1][3] = fmaf(x1, w.w, acc[1][3]);
        acc[2][0] = fmaf(x2, w.x, acc[2][0]); acc[2][1] = fmaf(x2, w.y, acc[2][1]);
        acc[2][2] = fmaf(x2, w.z, acc[2][2]); acc[2][3] = fmaf(x2, w.w, acc[2][3]);
        acc[3][0] = fmaf(x3, w.x, acc[3][0]); acc[3][1] = fmaf(x3, w.y, acc[3][1]);
        acc[3][2] = fmaf(x3, w.z, acc[3][2]); acc[3][3] = fmaf(x3, w.w, acc[3][3]);
    }
    #pragma unroll
    for (int i = 0; i < 4; i++)
        *(float4*)&Y[((size_t)(row0 + r0 + i)) * 64 + c0] =
            make_float4(acc[i][0], acc[i][1], acc[i][2], acc[i][3]);
}

// -------- single-pass online-softmax edge accumulate (4-lane groups, same branch per group) ----
#define ONLINE_EDGE(SRC, T, A0, A1, A2, A3, S, M) \
    do { \
        float ex; \
        if ((T) > (M)) { \
            float f = __expf((M) - (T)); \
            (S) *= f; \
            A0.x *= f; A0.y *= f; A0.z *= f; A0.w *= f; \
            A1.x *= f; A1.y *= f; A1.z *= f; A1.w *= f; \
            A2.x *= f; A2.y *= f; A2.z *= f; A2.w *= f; \
            A3.x *= f; A3.y *= f; A3.z *= f; A3.w *= f; \
            (M) = (T); ex = 1.f; \
        } else ex = __expf((T) - (M)); \
        (S) += ex; \
        size_t hbase = (size_t)(SRC) * 16 + gl * 4; \
        float4 h0 = H4[hbase], h1 = H4[hbase + 1], h2 = H4[hbase + 2], h3 = H4[hbase + 3]; \
        A0.x = fmaf(ex, h0.x, A0.x); A0.y = fmaf(ex, h0.y, A0.y); \
        A0.z = fmaf(ex, h0.z, A0.z); A0.w = fmaf(ex, h0.w, A0.w); \
        A1.x = fmaf(ex, h1.x, A1.x); A1.y = fmaf(ex, h1.y, A1.y); \
        A1.z = fmaf(ex, h1.z, A1.z); A1.w = fmaf(ex, h1.w, A1.w); \
        A2.x = fmaf(ex, h2.x, A2.x); A2.y = fmaf(ex, h2.y, A2.y); \
        A2.z = fmaf(ex, h2.z, A2.z); A2.w = fmaf(ex, h2.w, A2.w); \
        A3.x = fmaf(ex, h3.x, A3.x); A3.y = fmaf(ex, h3.y, A3.y); \
        A3.z = fmaf(ex, h3.z, A3.z); A3.w = fmaf(ex, h3.w, A3.w); \
    } while (0)

// ---------------- t/f aggregation: out = softmax-agg(hs) + b; one pass, no smem ----------------
__global__ void __launch_bounds__(512) agg_tf(int nA,
        const int* rpA, const int* csA, const float* ssA, const float* sdA,
        const float* hsA, const float* bA, float* YA,
        const float* vA0, float* oA0, const float* vA1, float* oA1,
        const int* rpB, const int* csB, const float* ssB, const float* sdB,
        const float* hsB, const float* bB, float* YB,
        const float* vB0, float* oB0, const float* vB1, float* oB1,
        int relu) {
    bool isA = (int)blockIdx.x < nA;
    int row0 = (isA ? blockIdx.x : blockIdx.x - nA) * 128;
    const int* rp = isA ? rpA : rpB;
    const int* cs = isA ? csA : csB;
    const float* ss = isA ? ssA : ssB;
    const float* sd = isA ? sdA : sdB;
    const float* hs = isA ? hsA : hsB;
    const float* b = isA ? bA : bB;
    float* Y = isA ? YA : YB;
    const float* v0 = isA ? vA0 : vB0;  float* o0 = isA ? oA0 : oB0;
    const float* v1 = isA ? vA1 : vB1;  float* o1 = isA ? oA1 : oB1;

    int tid = threadIdx.x;
    int g = tid >> 2, gl = tid & 3;
    int d = row0 + g;
    int beg = rp[d], end = rp[d + 1];
    float sdv = sd[d];
    float m = -1e30f, s = 0.f;
    float4 a0 = {0,0,0,0}, a1 = {0,0,0,0}, a2 = {0,0,0,0}, a3 = {0,0,0,0};
    const float4* H4 = (const float4*)hs;
    for (int j = beg; j < end; j++) {
        int src = cs[j];
        float t = ss[src] + sdv;
        t = t > 0.f ? t : 0.2f * t;
        ONLINE_EDGE(src, t, a0, a1, a2, a3, s, m);
    }
    float inv = s > 0.f ? 1.f / s : 0.f;
    const float4* B4 = (const float4*)b;
    float4 bb0 = B4[gl * 4], bb1 = B4[gl * 4 + 1], bb2 = B4[gl * 4 + 2], bb3 = B4[gl * 4 + 3];
    float4 ot[4];
    ot[0] = make_float4(a0.x * inv + bb0.x, a0.y * inv + bb0.y, a0.z * inv + bb0.z, a0.w * inv + bb0.w);
    ot[1] = make_float4(a1.x * inv + bb1.x, a1.y * inv + bb1.y, a1.z * inv + bb1.z, a1.w * inv + bb1.w);
    ot[2] = make_float4(a2.x * inv + bb2.x, a2.y * inv + bb2.y, a2.z * inv + bb2.z, a2.w * inv + bb2.w);
    ot[3] = make_float4(a3.x * inv + bb3.x, a3.y * inv + bb3.y, a3.z * inv + bb3.z, a3.w * inv + bb3.w);
    if (relu) {
        #pragma unroll
        for (int q = 0; q < 4; q++) {
            ot[q].x = fmaxf(ot[q].x, 0.f); ot[q].y = fmaxf(ot[q].y, 0.f);
            ot[q].z = fmaxf(ot[q].z, 0.f); ot[q].w = fmaxf(ot[q].w, 0.f);
        }
    }
    float4* Yr = (float4*)&Y[(size_t)d * 64];
    #pragma unroll
    for (int q = 0; q < 4; q++) Yr[gl * 4 + q] = ot[q];
#define DOT(v, o) { \
        const float4* V4 = (const float4*)v; \
        float dd = 0.f; \
        _Pragma("unroll") \
        for (int q = 0; q < 4; q++) { \
            float4 vv = V4[gl * 4 + q]; \
            dd += ot[q].x * vv.x + ot[q].y * vv.y + ot[q].z * vv.z + ot[q].w * vv.w; \
        } \
        dd += __shfl_xor_sync(FULLMASK, dd, 1); \
        dd += __shfl_xor_sync(FULLMASK, dd, 2); \
        if (gl == 0) o[d] = dd; }
    DOT(v0, o0)
    DOT(v1, o1)
#undef DOT
}

// ---------------- p-dst: one-pass online softmax-agg into smem -> two matmuls -> out + dots ----
__global__ void __launch_bounds__(256) gat_p(
        const int* rp1, const int* cs1, const float* ss1, const float* sd1,
        const float* X1, const float* W1,
        const int* rp2, const int* cs2, const float* ss2, const float* sd2,
        const float* X2, const float* W2,
        const float* b1, const float* b2,
        float* __restrict__ Y, int relu,
        const float* v0, float* o0, const float* v1, float* o1,
        const float* v2, float* o2, const float* v3, float* o3) {
    __shared__ float Zs[64 * 68];
    __shared__ float Wsh[64][68];
    int row0 = blockIdx.x * 64;
    int tid = threadIdx.x;
    int g = tid >> 2, gl = tid & 3;
    int tx = tid & 15, ty = tid >> 4;
    int c0 = tx * 4, r0 = ty * 4;
    float acc[4][4] = {};
    int d = row0 + g;
    for (int p = 0; p < 2; p++) {
        const int* rp = p ? rp2 : rp1;
        const int* cs = p ? cs2 : cs1;
        const float* ss = p ? ss2 : ss1;
        const float* sd = p ? sd2 : sd1;
        const float* X = p ? X2 : X1;
        const float* W = p ? W2 : W1;
        const float4* W4 = (const float4*)W;
        for (int i = tid; i < 1024; i += 256) {
            float4 v = W4[i];
            int r = i >> 4, c = (i & 15) * 4;
            Wsh[r][c] = v.x; Wsh[r][c + 1] = v.y; Wsh[r][c + 2] = v.z; Wsh[r][c + 3] = v.w;
        }
        int beg = rp[d], end = rp[d + 1];
        float sdv = sd[d];
        float m = -1e30f, s = 0.f;
        float4 a0 = {0,0,0,0}, a1 = {0,0,0,0}, a2 = {0,0,0,0}, a3 = {0,0,0,0};
        const float4* H4 = (const float4*)X;
        for (int j = beg; j < end; j++) {
            int src = cs[j];
            float t = ss[src] + sdv;
            t = t > 0.f ? t : 0.2f * t;
            ONLINE_EDGE(src, t, a0, a1, a2, a3, s, m);
        }
        float inv = s > 0.f ? 1.f / s : 0.f;
        float4* Zr = (float4*)&Zs[g * 68];
        Zr[gl * 4]     = make_float4(a0.x * inv, a0.y * inv, a0.z * inv, a0.w * inv);
        Zr[gl * 4 + 1] = make_float4(a1.x * inv, a1.y * inv, a1.z * inv, a1.w * inv);
        Zr[gl * 4 + 2] = make_float4(a2.x * inv, a2.y * inv, a2.z * inv, a2.w * inv);
        Zr[gl * 4 + 3] = make_float4(a3.x * inv, a3.y * inv, a3.z * inv, a3.w * inv);
        __syncthreads();
        #pragma unroll
        for (int k = 0; k < 64; k++) {
            float4 wv = *(const float4*)&Wsh[k][c0];
            float x0 = Zs[r0 * 68 + k], x1 = Zs[(r0 + 1) * 68 + k];
            float x2 = Zs[(r0 + 2) * 68 + k], x3 = Zs[(r0 + 3) * 68 + k];
            acc[0][0] = fmaf(x0, wv.x, acc[0][0]); acc[0][1] = fmaf(x0, wv.y, acc[0][1]);
            acc[0][2] = fmaf(x0, wv.z, acc[0][2]); acc[0][3] = fmaf(x0, wv.w, acc[0][3]);
            acc[1][0] = fmaf(x1, wv.x, acc[1][0]); acc[1][1] = fmaf(x1, wv.y, acc[1][1]);
            acc[1][2] = fmaf(x1, wv.z, acc[1][2]); acc[1][3] = fmaf(x1, wv.w, acc[1][3]);
            acc[2][0] = fmaf(x2, wv.x, acc[2][0]); acc[2][1] = fmaf(x2, wv.y, acc[2][1]);
            acc[2][2] = fmaf(x2, wv.z, acc[2][2]); acc[2][3] = fmaf(x2, wv.w, acc[2][3]);
            acc[3][0] = fmaf(x3, wv.x, acc[3][0]); acc[3][1] = fmaf(x3, wv.y, acc[3][1]);
            acc[3][2] = fmaf(x3, wv.z, acc[3][2]); acc[3][3] = fmaf(x3, wv.w, acc[3][3]);
        }
        __syncthreads();
    }
    #pragma unroll
    for (int i = 0; i < 4; i++)
        #pragma unroll
        for (int c = 0; c < 4; c++) {
            float v = acc[i][c] + b1[c0 + c] + b2[c0 + c];
            if (relu) v = fmaxf(v, 0.f);
            Zs[(r0 + i) * 68 + c0 + c] = v;
        }
    __syncthreads();
    float4 ot[4];
    const float4* Zr = (const float4*)&Zs[g * 68];
    #pragma unroll
    for (int q = 0; q < 4; q++) ot[q] = Zr[gl * 4 + q];
    float4* Yr = (float4*)&Y[(size_t)d * 64];
    #pragma unroll
    for (int q = 0; q < 4; q++) Yr[gl * 4 + q] = ot[q];
#define DOT(v, o) if (v) { \
        const float4* V4 = (const float4*)v; \
        float dd = 0.f; \
        _Pragma("unroll") \
        for (int q = 0; q < 4; q++) { \
            float4 vv = V4[gl * 4 + q]; \
            dd += ot[q].x * vv.x + ot[q].y * vv.y + ot[q].z * vv.z + ot[q].w * vv.w; \
        } \
        dd += __shfl_xor_sync(FULLMASK, dd, 1); \
        dd += __shfl_xor_sync(FULLMASK, dd, 2); \
        if (gl == 0) o[d] = dd; }
    DOT(v0, o0)
    DOT(v1, o1)
    DOT(v2, o2)
    DOT(v3, o3)
#undef DOT
}

// ---------------- pooling ----------------
__global__ void pool_k(const float* __restrict__ x, int npg, float* __restrict__ rep, int off) {
    int b = blockIdx.x;
    int t = threadIdx.x;            // 256
    int d = t & 63, c = t >> 6;
    const float* base = x + (size_t)b * npg * 64;
    float mx = -1e30f, mn = 1e30f, sm = 0.f;
    for (int n = c; n < npg; n += 4) {
        float v = base[(size_t)n * 64 + d];
        mx = fmaxf(mx, v); mn = fminf(mn, v); sm += v;
    }
    __shared__ float smx[4][64], smn[4][64], ssm[4][64];
    smx[c][d] = mx; smn[c][d] = mn; ssm[c][d] = sm;
    __syncthreads();
    if (c == 0) {
        for (int i = 1; i < 4; i++) {
            mx = fmaxf(mx, smx[i][d]); mn = fminf(mn, smn[i][d]); sm += ssm[i][d];
        }
        rep[b * 576 + off + d] = mx;
        rep[b * 576 + off + 64 + d] = mn;
        rep[b * 576 + off + 128 + d] = sm / (float)npg;
    }
}

// ---------------- LayerNorm + out_a projection ----------------
__global__ void ln_ra(const float* __restrict__ ap, const float* __restrict__ g,
                      const float* __restrict__ be, const float* __restrict__ Wa,
                      const float* __restrict__ ba, float* __restrict__ ra) {
    int idx = blockIdx.x * blockDim.x + threadIdx.x;
    int n = idx >> 5;
    if (n >= NPC) return;
    int lane = idx & 31;
    float2 v = *(const float2*)&ap[(size_t)n * 64 + lane * 2];
    float sum = v.x + v.y;
    for (int o = 16; o; o >>= 1) sum += __shfl_xor_sync(FULLMASK, sum, o);
    float mu = sum * (1.f / 64.f);
    float dx = v.x - mu, dy = v.y - mu;
    float vs = dx * dx + dy * dy;
    for (int o = 16; o; o >>= 1) vs += __shfl_xor_sync(FULLMASK, vs, o);
    float rs = rsqrtf(vs * (1.f / 64.f) + 1e-5f);
    float y0 = dx * rs * g[2 * lane] + be[2 * lane];
    float y1 = dy * rs * g[2 * lane + 1] + be[2 * lane + 1];
    float r0 = y0 * Wa[(2 * lane) * 2]     + y1 * Wa[(2 * lane + 1) * 2];
    float r1 = y0 * Wa[(2 * lane) * 2 + 1] + y1 * Wa[(2 * lane + 1) * 2 + 1];
    for (int o = 16; o; o >>= 1) r0 += __shfl_xor_sync(FULLMASK, r0, o);
    for (int o = 16; o; o >>= 1) r1 += __shfl_xor_sync(FULLMASK, r1, o);
    if (lane == 0) {
        ra[2 * n]     = r0 + ba[0];
        ra[2 * n + 1] = r1 + ba[1];
    }
}

// ---------------- per-graph softmax + scatter to actions ----------------
__device__ __forceinline__ float blk64_max(float v, volatile float* sh) {
    for (int o = 16; o; o >>= 1) v = fmaxf(v, __shfl_xor_sync(FULLMASK, v, o));
    if ((threadIdx.x & 31) == 0) sh[threadIdx.x >> 5] = v;
    __syncthreads();
    float r = fmaxf(sh[0], sh[1]);
    __syncthreads();
    return r;
}
__device__ __forceinline__ float blk64_sum(float v, volatile float* sh) {
    for (int o = 16; o; o >>= 1) v += __shfl_xor_sync(FULLMASK, v, o);
    if ((threadIdx.x & 31) == 0) sh[threadIdx.x >> 5] = v;
    __syncthreads();
    float r = sh[0] + sh[1];
    __syncthreads();
    return r;
}

__global__ void act_softmax(const float* __restrict__ ra, const int* __restrict__ part_id,
                            float* __restrict__ out) {
    __shared__ float sh[2];
    int b = blockIdx.x, t = threadIdx.x;        // 64
    int n = b * 64 + t;
    float v0 = ra[2 * n], v1 = ra[2 * n + 1];
    float m0 = blk64_max(v0, sh);
    float m1 = blk64_max(v1, sh);
    float e0 = expf(v0 - m0), e1 = expf(v1 - m1);
    float s0 = blk64_sum(e0, sh);
    float s1 = blk64_sum(e1, sh);
    int p = part_id[n];
    out[b * 128 + p] = e0 / s0;
    out[b * 128 + 64 + p] = e1 / s1;
}

// ---------------- value head MLPs ----------------
__global__ void mlp_k(const float* __restrict__ in, int K, const float* __restrict__ W,
                      const float* __restrict__ bias, float* __restrict__ out) {
    __shared__ float s[576];
    int b = blockIdx.x, j = threadIdx.x;        // 64
    for (int k = j; k < K; k += 64) s[k] = in[b * K + k];
    __syncthreads();
    float acc = bias[j];
    for (int k = 0; k < K; k++) acc = fmaf(s[k], W[k * 64 + j], acc);
    acc = 0.5f * acc * (1.f + erff(acc * 0.70710678118654752f));
    out[b * 64 + j] = acc;
}

__global__ void mlp_out(const float* __restrict__ h, const float* __restrict__ Wo,
                        const float* __restrict__ bo, float* __restrict__ V) {
    int idx = blockIdx.x * blockDim.x + threadIdx.x;
    int b = idx >> 5;
    if (b >= BC) return;
    int lane = idx & 31;
    float2 v = *(const float2*)&h[b * 64 + lane * 2];
    float s = v.x * Wo[2 * lane] + v.y * Wo[2 * lane + 1];
    for (int o = 16; o; o >>= 1) s += __shfl_xor_sync(FULLMASK, s, o);
    if (lane == 0) V[b] = tanhf(s + bo[0]);
}

// ---------------- host ----------------
#define SYMF(p, s) do { void* _q; cudaGetSymbolAddress(&_q, s); p = (float*)_q; } while (0)
#define SYMI(p, s) do { void* _q; cudaGetSymbolAddress(&_q, s); p = (int*)_q; } while (0)

extern "C" void kernel_launch(void* const* d_in, const int* in_sizes, int n_in,
                              void* d_out, int out_size) {
    const float* mass      = (const float*)d_in[0];
    const int*   pstate    = (const int*)d_in[1];
    const float* torque_x  = (const float*)d_in[2];
    const float* force_x   = (const float*)d_in[3];
    const int* e_pt_src = (const int*)d_in[4];
    const int* e_pt_dst = (const int*)d_in[5];
    const int* e_tp_src = (const int*)d_in[6];
    const int* e_tp_dst = (const int*)d_in[7];
    const int* e_pf_src = (const int*)d_in[8];
    const int* e_pf_dst = (const int*)d_in[9];
    const int* e_fp_src = (const int*)d_in[10];
    const int* e_fp_dst = (const int*)d_in[11];
    const int* part_id  = (const int*)d_in[13];
    const float* embW   = (const float*)d_in[14];
    const float* embS   = (const float*)d_in[15];
    const float* W_src  = (const float*)d_in[16];
    const float* W_dst  = (const float*)d_in[17];
    const float* a_src  = (const float*)d_in[18];
    const float* a_dst  = (const float*)d_in[19];
    const float* b_conv = (const float*)d_in[20];
    const float* ln_g   = (const float*)d_in[21];
    const float* ln_b   = (const float*)d_in[22];
    const float* outaW  = (const float*)d_in[23];
    const float* outab  = (const float*)d_in[24];
    const float* innW   = (const float*)d_in[25];
    const float* innb   = (const float*)d_in[26];
    const float* fulW   = (const float*)d_in[27];
    const float* fulb   = (const float*)d_in[28];
    const float* outW   = (const float*)d_in[29];
    const float* outb   = (const float*)d_in[30];
    float* out = (float*)d_out;

    float *xp, *xt, *xf, *ap, *hs0, *hs1;
    float *ss_pt, *ss_pf, *sd_tp, *sd_fp, *ss_tp, *sd_pt, *ss_fp, *sd_pf;
    float *wsv, *wdv, *ra, *rep, *h1, *h2;
    int *rp_pt, *rp_pf, *rp_tp, *rp_fp, *cs_pt, *cs_tp, *cs_pf, *cs_fp, *cnt;
    SYMF(xp, g_xp); SYMF(xt, g_xt); SYMF(xf, g_xf); SYMF(ap, g_ap);
    SYMF(hs0, g_hs0); SYMF(hs1, g_hs1);
    SYMF(ss_pt, g_ss_pt); SYMF(ss_pf, g_ss_pf); SYMF(sd_tp, g_sd_tp); SYMF(sd_fp, g_sd_fp);
    SYMF(ss_tp, g_ss_tp); SYMF(sd_pt, g_sd_pt); SYMF(ss_fp, g_ss_fp); SYMF(sd_pf, g_sd_pf);
    SYMF(wsv, g_wsv); SYMF(wdv, g_wdv); SYMF(ra, g_ra);
    SYMF(rep, g_rep); SYMF(h1, g_h1); SYMF(h2, g_h2);
    SYMI(rp_pt, g_rp_pt); SYMI(rp_pf, g_rp_pf); SYMI(rp_tp, g_rp_tp); SYMI(rp_fp, g_rp_fp);
    SYMI(cs_pt, g_cs_pt); SYMI(cs_tp, g_cs_tp); SYMI(cs_pf, g_cs_pf); SYMI(cs_fp, g_cs_fp);
    SYMI(cnt, g_cnt);

    // batched CSR build
    zero4<<<(4 * NTC) / 256, 256>>>(cnt);
    { dim3 g(EC / 256, 4); hist4<<<g, 256>>>(e_pt_dst, e_tp_dst, e_pf_dst, e_fp_dst, cnt); }
    scan4<<<4, 1024>>>(cnt, rp_pt, rp_tp, rp_pf, rp_fp);
    { dim3 g(EC / 256, 4);
      scatter4<<<g, 256>>>(e_pt_src, e_pt_dst, e_tp_src, e_tp_dst,
                           e_pf_src, e_pf_dst, e_fp_src, e_fp_dst,
                           rp_pt, rp_tp, rp_pf, rp_fp, cnt,
                           cs_pt, cs_tp, cs_pf, cs_fp); }

    // score vectors; embed; layer-0 score dots (buffer 0)
    vec_all<<<10, 256>>>(W_src, a_src, W_dst, a_dst, wsv, wdv);
    dot4<<<(NTC * 32) / 256, 256>>>(torque_x, NTC,
         wsv + 1 * 64, ss_tp, wdv + 0 * 64, sd_pt, nullptr, nullptr, nullptr, nullptr);
    dot4<<<(NFC * 32) / 256, 256>>>(force_x, NFC,
         wsv + 3 * 64, ss_fp, wdv + 2 * 64, sd_pf, nullptr, nullptr, nullptr, nullptr);
    embed_k<<<(NPC * 64) / 256, 256>>>(mass, pstate, embW, embS, xp);
    dot4<<<(NPC * 32) / 256, 256>>>(xp, NPC,
         wsv + 0 * 64, ss_pt, wsv + 2 * 64, ss_pf,
         wdv + 1 * 64, sd_tp, wdv + 3 * 64, sd_fp);

    for (int l = 0; l < 5; l++) {
        const float* xti = (l == 0) ? torque_x : xt;
        const float* xfi = (l == 0) ? force_x  : xf;
        const float* Wl = W_src + (size_t)l * 4 * 4096;
        const float* bl = b_conv + (size_t)l * 4 * 64;
        int relu = (l < 3) ? 1 : 0;
        int actor = (l == 4);
        const float* nwsv = wsv + (size_t)(l + 1) * 4 * 64;
        const float* nwdv = wdv + (size_t)(l + 1) * 4 * 64;
        int ci = l & 1, ni = (l + 1) & 1;
        const float* c_ss_pt = ss_pt + ci * NPC;  float* n_ss_pt = ss_pt + ni * NPC;
        const float* c_ss_pf = ss_pf + ci * NPC;  float* n_ss_pf = ss_pf + ni * NPC;
        const float* c_sd_tp = sd_tp + ci * NPC;  float* n_sd_tp = sd_tp + ni * NPC;
        const float* c_sd_fp = sd_fp + ci * NPC;  float* n_sd_fp = sd_fp + ni * NPC;
        const float* c_ss_tp = ss_tp + ci * NTC;  float* n_ss_tp = ss_tp + ni * NTC;
        const float* c_sd_pt = sd_pt + ci * NTC;  float* n_sd_pt = sd_pt + ni * NTC;
        const float* c_ss_fp = ss_fp + ci * NFC;  float* n_ss_fp = ss_fp + ni * NFC;
        const float* c_sd_pf = sd_pf + ci * NFC;  float* n_sd_pf = sd_pf + ni * NFC;

        if (!actor) {
            // 1) transform-first for t/f dst (reads xp BEFORE gat_p overwrites it)
            mm_hs<<<2 * (NPC / 64), 256>>>(xp, Wl + 0 * 4096, hs0, Wl + 2 * 4096, hs1);
            // 2) p-dst: consumes OLD xt/xf, writes new xp
            gat_p<<<NPC / 64, 256>>>(
                rp_tp, cs_tp, c_ss_tp, c_sd_tp, xti, Wl + 1 * 4096,
                rp_fp, cs_fp, c_ss_fp, c_sd_fp, xfi, Wl + 3 * 4096,
                bl + 1 * 64, bl + 3 * 64,
                xp, relu,
                nwsv + 0 * 64, n_ss_pt, nwsv + 2 * 64, n_ss_pf,
                nwdv + 1 * 64, n_sd_tp, nwdv + 3 * 64, n_sd_fp);
            // 3) t/f-dst: overwrites xt/xf IN PLACE (old values already consumed)
            agg_tf<<<NTC / 128 + NFC / 128, 512>>>(NTC / 128,
                rp_pt, cs_pt, c_ss_pt, c_sd_pt, hs0, bl + 0 * 64, xt,
                nwsv + 1 * 64, n_ss_tp, nwdv + 0 * 64, n_sd_pt,
                rp_pf, cs_pf, c_ss_pf, c_sd_pf, hs1, bl + 2 * 64, xf,
                nwsv + 3 * 64, n_ss_fp, nwdv + 2 * 64, n_sd_pf,
                relu);
        } else {
            gat_p<<<NPC / 64, 256>>>(
                rp_tp, cs_tp, c_ss_tp, c_sd_tp, xti, Wl + 1 * 4096,
                rp_fp, cs_fp, c_ss_fp, c_sd_fp, xfi, Wl + 3 * 4096,
                bl + 1 * 64, bl + 3 * 64,
                ap, 0,
                nullptr, nullptr, nullptr, nullptr,
                nullptr, nullptr, nullptr, nullptr);
        }
    }

    // pooling over final x (single buffers)
    pool_k<<<BC, 256>>>(xp, 64, rep, 0);
    pool_k<<<BC, 256>>>(xt, 512, rep, 192);
    pool_k<<<BC, 256>>>(xf, 512, rep, 384);

    // actor head
    ln_ra<<<(NPC * 32) / 256, 256>>>(ap, ln_g, ln_b, outaW, outab, ra);
    act_softmax<<<BC, 64>>>(ra, part_id, out);

    // value head
    mlp_k<<<BC, 64>>>(rep, 576, innW, innb, h1);
    mlp_k<<<BC, 64>>>(h1, 64, fulW, fulb, h2);
    mlp_out<<<(BC * 32) / 256, 256>>>(h2, outW, outb, out + BC * 128);
}

// round 11
// speedup vs baseline: 1.0722x; 1.0722x over previous
#include <cuda_runtime.h>
#include <math.h>

#define NPC 16384
#define NTC 131072
#define NFC 131072
#define EC  262144
#define BC  256
#define FULLMASK 0xffffffffu

// ---------------- device scratch ----------------
__device__ float g_xp[NPC * 64];
__device__ float g_xt[NTC * 64];        // single-buffered: gat_p reads before agg_tf overwrites
__device__ float g_xf[NFC * 64];
__device__ float g_ap[NPC * 64];
__device__ float g_hs0[NPC * 64];       // xp @ W[pt]
__device__ float g_hs1[NPC * 64];       // xp @ W[pf]
__device__ float g_ss_pt[2][NPC], g_ss_pf[2][NPC], g_sd_tp[2][NPC], g_sd_fp[2][NPC];
__device__ float g_ss_tp[2][NTC], g_sd_pt[2][NTC];
__device__ float g_ss_fp[2][NFC], g_sd_pf[2][NFC];
__device__ float g_wsv[5 * 4 * 64], g_wdv[5 * 4 * 64];
__device__ int g_rp_pt[NTC + 1], g_rp_pf[NFC + 1];
__device__ int g_rp_tp[NPC + 1], g_rp_fp[NPC + 1];
__device__ int g_cs_pt[EC], g_cs_tp[EC], g_cs_pf[EC], g_cs_fp[EC];
__device__ int g_cnt[4 * NTC];
__device__ float g_ra[NPC * 2];
__device__ float g_rep[BC * 576];
__device__ float g_h1[BC * 64], g_h2[BC * 64];

// ---------------- batched CSR build ----------------
__global__ void zero4(int* c) {
    int i = blockIdx.x * blockDim.x + threadIdx.x;
    if (i < 4 * NTC) c[i] = 0;
}

__global__ void hist4(const int* __restrict__ d0, const int* __restrict__ d1,
                      const int* __restrict__ d2, const int* __restrict__ d3,
                      int* __restrict__ cnt) {
    int t = blockIdx.y;
    const int* d = (t == 0) ? d0 : (t == 1) ? d1 : (t == 2) ? d2 : d3;
    int* c = cnt + t * NTC;
    int i = blockIdx.x * blockDim.x + threadIdx.x;
    if (i < EC) atomicAdd(&c[d[i]], 1);
}

__device__ void scan_body(const int* __restrict__ deg, int* __restrict__ rowptr,
                          int* __restrict__ rezero, int n) {
    __shared__ int warp_sums[32];
    __shared__ int s_carry;
    int tid = threadIdx.x;
    int lane = tid & 31, wid = tid >> 5;
    if (tid == 0) s_carry = 0;
    __syncthreads();
    for (int base = 0; base < n; base += 1024) {
        int i = base + tid;
        int v = (i < n) ? deg[i] : 0;
        int x = v;
        #pragma unroll
        for (int off = 1; off < 32; off <<= 1) {
            int y = __shfl_up_sync(FULLMASK, x, off);
            if (lane >= off) x += y;
        }
        if (lane == 31) warp_sums[wid] = x;
        __syncthreads();
        if (tid < 32) {
            int s = warp_sums[tid];
            #pragma unroll
            for (int off = 1; off < 32; off <<= 1) {
                int y = __shfl_up_sync(FULLMASK, s, off);
                if (tid >= off) s += y;
            }
            warp_sums[tid] = s;
        }
        __syncthreads();
        int incl = x + (wid ? warp_sums[wid - 1] : 0);
        if (i < n) { rowptr[i] = s_carry + incl - v; rezero[i] = 0; }
        int chunk_total = warp_sums[31];
        __syncthreads();
        if (tid == 0) s_carry += chunk_total;
        __syncthreads();
    }
    if (tid == 0) rowptr[n] = s_carry;
}

__global__ void scan4(int* __restrict__ cnt,
                      int* rp0, int* rp1, int* rp2, int* rp3) {
    int t = blockIdx.x;
    int* rp = (t == 0) ? rp0 : (t == 1) ? rp1 : (t == 2) ? rp2 : rp3;
    int n = (t == 0) ? NTC : (t == 1) ? NPC : (t == 2) ? NFC : NPC;
    scan_body(cnt + t * NTC, rp, cnt + t * NTC, n);
}

__global__ void scatter4(const int* __restrict__ s0, const int* __restrict__ d0,
                         const int* __restrict__ s1, const int* __restrict__ d1,
                         const int* __restrict__ s2, const int* __restrict__ d2,
                         const int* __restrict__ s3, const int* __restrict__ d3,
                         const int* rp0, const int* rp1, const int* rp2, const int* rp3,
                         int* __restrict__ cnt,
                         int* c0, int* c1, int* c2, int* c3) {
    int t = blockIdx.y;
    const int* src = (t == 0) ? s0 : (t == 1) ? s1 : (t == 2) ? s2 : s3;
    const int* dst = (t == 0) ? d0 : (t == 1) ? d1 : (t == 2) ? d2 : d3;
    const int* rp  = (t == 0) ? rp0 : (t == 1) ? rp1 : (t == 2) ? rp2 : rp3;
    int* csr = (t == 0) ? c0 : (t == 1) ? c1 : (t == 2) ? c2 : c3;
    int* cur = cnt + t * NTC;
    int i = blockIdx.x * blockDim.x + threadIdx.x;
    if (i >= EC) return;
    int d = dst[i];
    int pos = rp[d] + atomicAdd(&cur[d], 1);
    csr[pos] = src[i];
}

// ---------------- score vectors for ALL layers ----------------
__global__ void vec_all(const float* __restrict__ Ws, const float* __restrict__ as,
                        const float* __restrict__ Wd, const float* __restrict__ ad,
                        float* __restrict__ wsv, float* __restrict__ wdv) {
    int idx = blockIdx.x * blockDim.x + threadIdx.x;
    if (idx >= 2 * 5 * 4 * 64) return;
    int which = idx >= 1280;
    int r = which ? idx - 1280 : idx;
    int i = r & 63, lt = r >> 6;
    const float* W = which ? Wd : Ws;
    const float* a = which ? ad : as;
    float* o = which ? wdv : wsv;
    float acc = 0.f;
    const float* wr = W + (size_t)(lt * 64 + i) * 64;
    const float* ar = a + lt * 64;
    #pragma unroll 8
    for (int j = 0; j < 64; j++) acc = fmaf(wr[j], ar[j], acc);
    o[r] = acc;
}

// ---------------- embed ----------------
__global__ void embed_k(const float* __restrict__ mass, const int* __restrict__ pstate,
                        const float* __restrict__ embW, const float* __restrict__ embS,
                        float* __restrict__ xp) {
    int idx = blockIdx.x * blockDim.x + threadIdx.x;
    if (idx >= NPC * 64) return;
    int n = idx >> 6, j = idx & 63;
    float v;
    if (j < 32) v = mass[n] * embW[j];
    else {
        int st = pstate[2 * n] + 2 * pstate[2 * n + 1];
        v = embS[st * 32 + (j - 32)];
    }
    xp[idx] = v;
}

// ---------------- up to 4 per-row dot products (layer-0 init) ----------------
__global__ void dot4(const float* __restrict__ X, int n,
                     const float* v0, float* o0, const float* v1, float* o1,
                     const float* v2, float* o2, const float* v3, float* o3) {
    int idx = blockIdx.x * blockDim.x + threadIdx.x;
    int w = idx >> 5;
    if (w >= n) return;
    int lane = idx & 31;
    float2 x = *(const float2*)&X[(size_t)w * 64 + lane * 2];
#define DODOT(v, o) if (v) { \
        float s = x.x * v[2 * lane] + x.y * v[2 * lane + 1]; \
        for (int off = 16; off; off >>= 1) s += __shfl_xor_sync(FULLMASK, s, off); \
        if (lane == 0) o[w] = s; }
    DODOT(v0, o0)
    DODOT(v1, o1)
    DODOT(v2, o2)
    DODOT(v3, o3)
#undef DODOT
}

// ---------------- hs matmul: hs0 = X@W0, hs1 = X@W1 (blockIdx split) ----------------
__global__ void __launch_bounds__(256) mm_hs(const float* __restrict__ X,
                                             const float* __restrict__ W0, float* __restrict__ Y0,
                                             const float* __restrict__ W1, float* __restrict__ Y1) {
    __shared__ float Xs[64][65];
    __shared__ float Wsh[64][68];
    int half = blockIdx.x >= (NPC / 64);
    int row0 = (half ? blockIdx.x - NPC / 64 : blockIdx.x) * 64;
    const float* W = half ? W1 : W0;
    float* Y = half ? Y1 : Y0;
    int tid = threadIdx.x;
    const float4* W4 = (const float4*)W;
    for (int i = tid; i < 1024; i += 256) {
        float4 v = W4[i];
        int r = i >> 4, c = (i & 15) * 4;
        Wsh[r][c] = v.x; Wsh[r][c + 1] = v.y; Wsh[r][c + 2] = v.z; Wsh[r][c + 3] = v.w;
    }
    const float4* X4 = (const float4*)(X + (size_t)row0 * 64);
    for (int i = tid; i < 1024; i += 256) {
        float4 v = X4[i];
        int r = i >> 4, c = (i & 15) * 4;
        Xs[r][c] = v.x; Xs[r][c + 1] = v.y; Xs[r][c + 2] = v.z; Xs[r][c + 3] = v.w;
    }
    __syncthreads();
    int tx = tid & 15, ty = tid >> 4;
    int c0 = tx * 4, r0 = ty * 4;
    float acc[4][4] = {};
    #pragma unroll
    for (int k = 0; k < 64; k++) {
        float4 w = *(const float4*)&Wsh[k][c0];
        float x0 = Xs[r0][k], x1 = Xs[r0 + 1][k], x2 = Xs[r0 + 2][k], x3 = Xs[r0 + 3][k];
        acc[0][0] = fmaf(x0, w.x, acc[0][0]); acc[0][1] = fmaf(x0, w.y, acc[0][1]);
        acc[0][2] = fmaf(x0, w.z, acc[0][2]); acc[0][3] = fmaf(x0, w.w, acc[0][3]);
        acc[1][0] = fmaf(x1, w.x, acc[1][0]); acc[1][1] = fmaf(x1, w.y, acc[1][1]);
        acc[1][2] = fmaf(x1, w.z, acc[1][2]); acc[1][3] = fmaf(x1, w.w, acc[1][3]);
        acc[2][0] = fmaf(x2, w.x, acc[2][0]); acc[2][1] = fmaf(x2, w.y, acc[2][1]);
        acc[2][2] = fmaf(x2, w.z, acc[2][2]); acc[2][3] = fmaf(x2, w.w, acc[2][3]);
        acc[3][0] = fmaf(x3, w.x, acc[3][0]); acc[3][1] = fmaf(x3, w.y, acc[3][1]);
        acc[3][2] = fmaf(x3, w.z, acc[3][2]); acc[3][3] = fmaf(x3, w.w, acc[3][3]);
    }
    #pragma unroll
    for (int i = 0; i < 4; i++)
        *(float4*)&Y[((size_t)(row0 + r0 + i)) * 64 + c0] =
            make_float4(acc[i][0], acc[i][1], acc[i][2], acc[i][3]);
}

// -------- two-pass softmax-agg for one row with a 4-lane group.
// Pass 1: lane-strided max + 2-shfl group reduce (no serial chain).
// Pass 2: fixed-max exp + gather; every exp independent -> pipelined.
// All macro locals prefixed _ga_ to avoid shadowing the caller's sOut variable.
#define GROUP_AGG(rp, cs, ss, sd, H4, a0, a1, a2, a3, sOut, dRow) \
    { \
        int _ga_beg = rp[dRow], _ga_end = rp[dRow + 1]; \
        float _ga_sdv = sd[dRow]; \
        float _ga_m = -1e30f; \
        for (int _ga_j = _ga_beg + gl; _ga_j < _ga_end; _ga_j += 4) { \
            float _ga_t = ss[cs[_ga_j]] + _ga_sdv; \
            _ga_t = _ga_t > 0.f ? _ga_t : 0.2f * _ga_t; \
            _ga_m = fmaxf(_ga_m, _ga_t); \
        } \
        _ga_m = fmaxf(_ga_m, __shfl_xor_sync(FULLMASK, _ga_m, 1)); \
        _ga_m = fmaxf(_ga_m, __shfl_xor_sync(FULLMASK, _ga_m, 2)); \
        float _ga_s = 0.f; \
        _Pragma("unroll 2") \
        for (int _ga_j = _ga_beg; _ga_j < _ga_end; _ga_j++) { \
            int _ga_src = cs[_ga_j]; \
            float _ga_t = ss[_ga_src] + _ga_sdv; \
            _ga_t = _ga_t > 0.f ? _ga_t : 0.2f * _ga_t; \
            float _ga_ex = __expf(_ga_t - _ga_m); \
            _ga_s += _ga_ex; \
            size_t _ga_hb = (size_t)_ga_src * 16 + gl * 4; \
            float4 _ga_h0 = H4[_ga_hb], _ga_h1 = H4[_ga_hb + 1]; \
            float4 _ga_h2 = H4[_ga_hb + 2], _ga_h3 = H4[_ga_hb + 3]; \
            a0.x = fmaf(_ga_ex, _ga_h0.x, a0.x); a0.y = fmaf(_ga_ex, _ga_h0.y, a0.y); \
            a0.z = fmaf(_ga_ex, _ga_h0.z, a0.z); a0.w = fmaf(_ga_ex, _ga_h0.w, a0.w); \
            a1.x = fmaf(_ga_ex, _ga_h1.x, a1.x); a1.y = fmaf(_ga_ex, _ga_h1.y, a1.y); \
            a1.z = fmaf(_ga_ex, _ga_h1.z, a1.z); a1.w = fmaf(_ga_ex, _ga_h1.w, a1.w); \
            a2.x = fmaf(_ga_ex, _ga_h2.x, a2.x); a2.y = fmaf(_ga_ex, _ga_h2.y, a2.y); \
            a2.z = fmaf(_ga_ex, _ga_h2.z, a2.z); a2.w = fmaf(_ga_ex, _ga_h2.w, a2.w); \
            a3.x = fmaf(_ga_ex, _ga_h3.x, a3.x); a3.y = fmaf(_ga_ex, _ga_h3.y, a3.y); \
            a3.z = fmaf(_ga_ex, _ga_h3.z, a3.z); a3.w = fmaf(_ga_ex, _ga_h3.w, a3.w); \
        } \
        sOut = _ga_s; \
    }

// ---------------- t/f aggregation: out = softmax-agg(hs) + b; no smem ----------------
__global__ void __launch_bounds__(512) agg_tf(int nA,
        const int* rpA, const int* csA, const float* ssA, const float* sdA,
        const float* hsA, const float* bA, float* YA,
        const float* vA0, float* oA0, const float* vA1, float* oA1,
        const int* rpB, const int* csB, const float* ssB, const float* sdB,
        const float* hsB, const float* bB, float* YB,
        const float* vB0, float* oB0, const float* vB1, float* oB1,
        int relu) {
    bool isA = (int)blockIdx.x < nA;
    int row0 = (isA ? blockIdx.x : blockIdx.x - nA) * 128;
    const int* rp = isA ? rpA : rpB;
    const int* cs = isA ? csA : csB;
    const float* ss = isA ? ssA : ssB;
    const float* sd = isA ? sdA : sdB;
    const float* hs = isA ? hsA : hsB;
    const float* b = isA ? bA : bB;
    float* Y = isA ? YA : YB;
    const float* v0 = isA ? vA0 : vB0;  float* o0 = isA ? oA0 : oB0;
    const float* v1 = isA ? vA1 : vB1;  float* o1 = isA ? oA1 : oB1;

    int tid = threadIdx.x;
    int g = tid >> 2, gl = tid & 3;
    int d = row0 + g;
    float s;
    float4 a0 = {0,0,0,0}, a1 = {0,0,0,0}, a2 = {0,0,0,0}, a3 = {0,0,0,0};
    const float4* H4 = (const float4*)hs;
    GROUP_AGG(rp, cs, ss, sd, H4, a0, a1, a2, a3, s, d);
    float inv = s > 0.f ? 1.f / s : 0.f;
    const float4* B4 = (const float4*)b;
    float4 bb0 = B4[gl * 4], bb1 = B4[gl * 4 + 1], bb2 = B4[gl * 4 + 2], bb3 = B4[gl * 4 + 3];
    float4 ot[4];
    ot[0] = make_float4(a0.x * inv + bb0.x, a0.y * inv + bb0.y, a0.z * inv + bb0.z, a0.w * inv + bb0.w);
    ot[1] = make_float4(a1.x * inv + bb1.x, a1.y * inv + bb1.y, a1.z * inv + bb1.z, a1.w * inv + bb1.w);
    ot[2] = make_float4(a2.x * inv + bb2.x, a2.y * inv + bb2.y, a2.z * inv + bb2.z, a2.w * inv + bb2.w);
    ot[3] = make_float4(a3.x * inv + bb3.x, a3.y * inv + bb3.y, a3.z * inv + bb3.z, a3.w * inv + bb3.w);
    if (relu) {
        #pragma unroll
        for (int q = 0; q < 4; q++) {
            ot[q].x = fmaxf(ot[q].x, 0.f); ot[q].y = fmaxf(ot[q].y, 0.f);
            ot[q].z = fmaxf(ot[q].z, 0.f); ot[q].w = fmaxf(ot[q].w, 0.f);
        }
    }
    float4* Yr = (float4*)&Y[(size_t)d * 64];
    #pragma unroll
    for (int q = 0; q < 4; q++) Yr[gl * 4 + q] = ot[q];
#define DOT(v, o) { \
        const float4* V4 = (const float4*)v; \
        float dd = 0.f; \
        _Pragma("unroll") \
        for (int q = 0; q < 4; q++) { \
            float4 vv = V4[gl * 4 + q]; \
            dd += ot[q].x * vv.x + ot[q].y * vv.y + ot[q].z * vv.z + ot[q].w * vv.w; \
        } \
        dd += __shfl_xor_sync(FULLMASK, dd, 1); \
        dd += __shfl_xor_sync(FULLMASK, dd, 2); \
        if (gl == 0) o[d] = dd; }
    DOT(v0, o0)
    DOT(v1, o1)
#undef DOT
}

// ---------------- p-dst: two-pass agg into smem -> two matmuls -> out + dots ----
__global__ void __launch_bounds__(256) gat_p(
        const int* rp1, const int* cs1, const float* ss1, const float* sd1,
        const float* X1, const float* W1,
        const int* rp2, const int* cs2, const float* ss2, const float* sd2,
        const float* X2, const float* W2,
        const float* b1, const float* b2,
        float* __restrict__ Y, int relu,
        const float* v0, float* o0, const float* v1, float* o1,
        const float* v2, float* o2, const float* v3, float* o3) {
    __shared__ float Zs[64 * 68];
    __shared__ float Wsh[64][68];
    int row0 = blockIdx.x * 64;
    int tid = threadIdx.x;
    int g = tid >> 2, gl = tid & 3;
    int tx = tid & 15, ty = tid >> 4;
    int c0 = tx * 4, r0 = ty * 4;
    float acc[4][4] = {};
    int d = row0 + g;
    for (int p = 0; p < 2; p++) {
        const int* rp = p ? rp2 : rp1;
        const int* cs = p ? cs2 : cs1;
        const float* ss = p ? ss2 : ss1;
        const float* sd = p ? sd2 : sd1;
        const float* X = p ? X2 : X1;
        const float* W = p ? W2 : W1;
        const float4* W4 = (const float4*)W;
        for (int i = tid; i < 1024; i += 256) {
            float4 v = W4[i];
            int r = i >> 4, c = (i & 15) * 4;
            Wsh[r][c] = v.x; Wsh[r][c + 1] = v.y; Wsh[r][c + 2] = v.z; Wsh[r][c + 3] = v.w;
        }
        float s;
        float4 a0 = {0,0,0,0}, a1 = {0,0,0,0}, a2 = {0,0,0,0}, a3 = {0,0,0,0};
        const float4* H4 = (const float4*)X;
        GROUP_AGG(rp, cs, ss, sd, H4, a0, a1, a2, a3, s, d);
        float inv = s > 0.f ? 1.f / s : 0.f;
        float4* Zr = (float4*)&Zs[g * 68];
        Zr[gl * 4]     = make_float4(a0.x * inv, a0.y * inv, a0.z * inv, a0.w * inv);
        Zr[gl * 4 + 1] = make_float4(a1.x * inv, a1.y * inv, a1.z * inv, a1.w * inv);
        Zr[gl * 4 + 2] = make_float4(a2.x * inv, a2.y * inv, a2.z * inv, a2.w * inv);
        Zr[gl * 4 + 3] = make_float4(a3.x * inv, a3.y * inv, a3.z * inv, a3.w * inv);
        __syncthreads();
        #pragma unroll
        for (int k = 0; k < 64; k++) {
            float4 wv = *(const float4*)&Wsh[k][c0];
            float x0 = Zs[r0 * 68 + k], x1 = Zs[(r0 + 1) * 68 + k];
            float x2 = Zs[(r0 + 2) * 68 + k], x3 = Zs[(r0 + 3) * 68 + k];
            acc[0][0] = fmaf(x0, wv.x, acc[0][0]); acc[0][1] = fmaf(x0, wv.y, acc[0][1]);
            acc[0][2] = fmaf(x0, wv.z, acc[0][2]); acc[0][3] = fmaf(x0, wv.w, acc[0][3]);
            acc[1][0] = fmaf(x1, wv.x, acc[1][0]); acc[1][1] = fmaf(x1, wv.y, acc[1][1]);
            acc[1][2] = fmaf(x1, wv.z, acc[1][2]); acc[1][3] = fmaf(x1, wv.w, acc[1][3]);
            acc[2][0] = fmaf(x2, wv.x, acc[2][0]); acc[2][1] = fmaf(x2, wv.y, acc[2][1]);
            acc[2][2] = fmaf(x2, wv.z, acc[2][2]); acc[2][3] = fmaf(x2, wv.w, acc[2][3]);
            acc[3][0] = fmaf(x3, wv.x, acc[3][0]); acc[3][1] = fmaf(x3, wv.y, acc[3][1]);
            acc[3][2] = fmaf(x3, wv.z, acc[3][2]); acc[3][3] = fmaf(x3, wv.w, acc[3][3]);
        }
        __syncthreads();
    }
    #pragma unroll
    for (int i = 0; i < 4; i++)
        #pragma unroll
        for (int c = 0; c < 4; c++) {
            float v = acc[i][c] + b1[c0 + c] + b2[c0 + c];
            if (relu) v = fmaxf(v, 0.f);
            Zs[(r0 + i) * 68 + c0 + c] = v;
        }
    __syncthreads();
    float4 ot[4];
    const float4* Zr = (const float4*)&Zs[g * 68];
    #pragma unroll
    for (int q = 0; q < 4; q++) ot[q] = Zr[gl * 4 + q];
    float4* Yr = (float4*)&Y[(size_t)d * 64];
    #pragma unroll
    for (int q = 0; q < 4; q++) Yr[gl * 4 + q] = ot[q];
#define DOT(v, o) if (v) { \
        const float4* V4 = (const float4*)v; \
        float dd = 0.f; \
        _Pragma("unroll") \
        for (int q = 0; q < 4; q++) { \
            float4 vv = V4[gl * 4 + q]; \
            dd += ot[q].x * vv.x + ot[q].y * vv.y + ot[q].z * vv.z + ot[q].w * vv.w; \
        } \
        dd += __shfl_xor_sync(FULLMASK, dd, 1); \
        dd += __shfl_xor_sync(FULLMASK, dd, 2); \
        if (gl == 0) o[d] = dd; }
    DOT(v0, o0)
    DOT(v1, o1)
    DOT(v2, o2)
    DOT(v3, o3)
#undef DOT
}

// ---------------- pooling ----------------
__global__ void pool_k(const float* __restrict__ x, int npg, float* __restrict__ rep, int off) {
    int b = blockIdx.x;
    int t = threadIdx.x;            // 256
    int d = t & 63, c = t >> 6;
    const float* base = x + (size_t)b * npg * 64;
    float mx = -1e30f, mn = 1e30f, sm = 0.f;
    for (int n = c; n < npg; n += 4) {
        float v = base[(size_t)n * 64 + d];
        mx = fmaxf(mx, v); mn = fminf(mn, v); sm += v;
    }
    __shared__ float smx[4][64], smn[4][64], ssm[4][64];
    smx[c][d] = mx; smn[c][d] = mn; ssm[c][d] = sm;
    __syncthreads();
    if (c == 0) {
        for (int i = 1; i < 4; i++) {
            mx = fmaxf(mx, smx[i][d]); mn = fminf(mn, smn[i][d]); sm += ssm[i][d];
        }
        rep[b * 576 + off + d] = mx;
        rep[b * 576 + off + 64 + d] = mn;
        rep[b * 576 + off + 128 + d] = sm / (float)npg;
    }
}

// ---------------- LayerNorm + out_a projection ----------------
__global__ void ln_ra(const float* __restrict__ ap, const float* __restrict__ g,
                      const float* __restrict__ be, const float* __restrict__ Wa,
                      const float* __restrict__ ba, float* __restrict__ ra) {
    int idx = blockIdx.x * blockDim.x + threadIdx.x;
    int n = idx >> 5;
    if (n >= NPC) return;
    int lane = idx & 31;
    float2 v = *(const float2*)&ap[(size_t)n * 64 + lane * 2];
    float sum = v.x + v.y;
    for (int o = 16; o; o >>= 1) sum += __shfl_xor_sync(FULLMASK, sum, o);
    float mu = sum * (1.f / 64.f);
    float dx = v.x - mu, dy = v.y - mu;
    float vs = dx * dx + dy * dy;
    for (int o = 16; o; o >>= 1) vs += __shfl_xor_sync(FULLMASK, vs, o);
    float rs = rsqrtf(vs * (1.f / 64.f) + 1e-5f);
    float y0 = dx * rs * g[2 * lane] + be[2 * lane];
    float y1 = dy * rs * g[2 * lane + 1] + be[2 * lane + 1];
    float r0 = y0 * Wa[(2 * lane) * 2]     + y1 * Wa[(2 * lane + 1) * 2];
    float r1 = y0 * Wa[(2 * lane) * 2 + 1] + y1 * Wa[(2 * lane + 1) * 2 + 1];
    for (int o = 16; o; o >>= 1) r0 += __shfl_xor_sync(FULLMASK, r0, o);
    for (int o = 16; o; o >>= 1) r1 += __shfl_xor_sync(FULLMASK, r1, o);
    if (lane == 0) {
        ra[2 * n]     = r0 + ba[0];
        ra[2 * n + 1] = r1 + ba[1];
    }
}

// ---------------- per-graph softmax + scatter to actions ----------------
__device__ __forceinline__ float blk64_max(float v, volatile float* sh) {
    for (int o = 16; o; o >>= 1) v = fmaxf(v, __shfl_xor_sync(FULLMASK, v, o));
    if ((threadIdx.x & 31) == 0) sh[threadIdx.x >> 5] = v;
    __syncthreads();
    float r = fmaxf(sh[0], sh[1]);
    __syncthreads();
    return r;
}
__device__ __forceinline__ float blk64_sum(float v, volatile float* sh) {
    for (int o = 16; o; o >>= 1) v += __shfl_xor_sync(FULLMASK, v, o);
    if ((threadIdx.x & 31) == 0) sh[threadIdx.x >> 5] = v;
    __syncthreads();
    float r = sh[0] + sh[1];
    __syncthreads();
    return r;
}

__global__ void act_softmax(const float* __restrict__ ra, const int* __restrict__ part_id,
                            float* __restrict__ out) {
    __shared__ float sh[2];
    int b = blockIdx.x, t = threadIdx.x;        // 64
    int n = b * 64 + t;
    float v0 = ra[2 * n], v1 = ra[2 * n + 1];
    float m0 = blk64_max(v0, sh);
    float m1 = blk64_max(v1, sh);
    float e0 = expf(v0 - m0), e1 = expf(v1 - m1);
    float s0 = blk64_sum(e0, sh);
    float s1 = blk64_sum(e1, sh);
    int p = part_id[n];
    out[b * 128 + p] = e0 / s0;
    out[b * 128 + 64 + p] = e1 / s1;
}

// ---------------- value head MLPs ----------------
__global__ void mlp_k(const float* __restrict__ in, int K, const float* __restrict__ W,
                      const float* __restrict__ bias, float* __restrict__ out) {
    __shared__ float s[576];
    int b = blockIdx.x, j = threadIdx.x;        // 64
    for (int k = j; k < K; k += 64) s[k] = in[b * K + k];
    __syncthreads();
    float acc = bias[j];
    for (int k = 0; k < K; k++) acc = fmaf(s[k], W[k * 64 + j], acc);
    acc = 0.5f * acc * (1.f + erff(acc * 0.70710678118654752f));
    out[b * 64 + j] = acc;
}

__global__ void mlp_out(const float* __restrict__ h, const float* __restrict__ Wo,
                        const float* __restrict__ bo, float* __restrict__ V) {
    int idx = blockIdx.x * blockDim.x + threadIdx.x;
    int b = idx >> 5;
    if (b >= BC) return;
    int lane = idx & 31;
    float2 v = *(const float2*)&h[b * 64 + lane * 2];
    float s = v.x * Wo[2 * lane] + v.y * Wo[2 * lane + 1];
    for (int o = 16; o; o >>= 1) s += __shfl_xor_sync(FULLMASK, s, o);
    if (lane == 0) V[b] = tanhf(s + bo[0]);
}

// ---------------- host ----------------
#define SYMF(p, s) do { void* _q; cudaGetSymbolAddress(&_q, s); p = (float*)_q; } while (0)
#define SYMI(p, s) do { void* _q; cudaGetSymbolAddress(&_q, s); p = (int*)_q; } while (0)

extern "C" void kernel_launch(void* const* d_in, const int* in_sizes, int n_in,
                              void* d_out, int out_size) {
    const float* mass      = (const float*)d_in[0];
    const int*   pstate    = (const int*)d_in[1];
    const float* torque_x  = (const float*)d_in[2];
    const float* force_x   = (const float*)d_in[3];
    const int* e_pt_src = (const int*)d_in[4];
    const int* e_pt_dst = (const int*)d_in[5];
    const int* e_tp_src = (const int*)d_in[6];
    const int* e_tp_dst = (const int*)d_in[7];
    const int* e_pf_src = (const int*)d_in[8];
    const int* e_pf_dst = (const int*)d_in[9];
    const int* e_fp_src = (const int*)d_in[10];
    const int* e_fp_dst = (const int*)d_in[11];
    const int* part_id  = (const int*)d_in[13];
    const float* embW   = (const float*)d_in[14];
    const float* embS   = (const float*)d_in[15];
    const float* W_src  = (const float*)d_in[16];
    const float* W_dst  = (const float*)d_in[17];
    const float* a_src  = (const float*)d_in[18];
    const float* a_dst  = (const float*)d_in[19];
    const float* b_conv = (const float*)d_in[20];
    const float* ln_g   = (const float*)d_in[21];
    const float* ln_b   = (const float*)d_in[22];
    const float* outaW  = (const float*)d_in[23];
    const float* outab  = (const float*)d_in[24];
    const float* innW   = (const float*)d_in[25];
    const float* innb   = (const float*)d_in[26];
    const float* fulW   = (const float*)d_in[27];
    const float* fulb   = (const float*)d_in[28];
    const float* outW   = (const float*)d_in[29];
    const float* outb   = (const float*)d_in[30];
    float* out = (float*)d_out;

    float *xp, *xt, *xf, *ap, *hs0, *hs1;
    float *ss_pt, *ss_pf, *sd_tp, *sd_fp, *ss_tp, *sd_pt, *ss_fp, *sd_pf;
    float *wsv, *wdv, *ra, *rep, *h1, *h2;
    int *rp_pt, *rp_pf, *rp_tp, *rp_fp, *cs_pt, *cs_tp, *cs_pf, *cs_fp, *cnt;
    SYMF(xp, g_xp); SYMF(xt, g_xt); SYMF(xf, g_xf); SYMF(ap, g_ap);
    SYMF(hs0, g_hs0); SYMF(hs1, g_hs1);
    SYMF(ss_pt, g_ss_pt); SYMF(ss_pf, g_ss_pf); SYMF(sd_tp, g_sd_tp); SYMF(sd_fp, g_sd_fp);
    SYMF(ss_tp, g_ss_tp); SYMF(sd_pt, g_sd_pt); SYMF(ss_fp, g_ss_fp); SYMF(sd_pf, g_sd_pf);
    SYMF(wsv, g_wsv); SYMF(wdv, g_wdv); SYMF(ra, g_ra);
    SYMF(rep, g_rep); SYMF(h1, g_h1); SYMF(h2, g_h2);
    SYMI(rp_pt, g_rp_pt); SYMI(rp_pf, g_rp_pf); SYMI(rp_tp, g_rp_tp); SYMI(rp_fp, g_rp_fp);
    SYMI(cs_pt, g_cs_pt); SYMI(cs_tp, g_cs_tp); SYMI(cs_pf, g_cs_pf); SYMI(cs_fp, g_cs_fp);
    SYMI(cnt, g_cnt);

    // batched CSR build
    zero4<<<(4 * NTC) / 256, 256>>>(cnt);
    { dim3 g(EC / 256, 4); hist4<<<g, 256>>>(e_pt_dst, e_tp_dst, e_pf_dst, e_fp_dst, cnt); }
    scan4<<<4, 1024>>>(cnt, rp_pt, rp_tp, rp_pf, rp_fp);
    { dim3 g(EC / 256, 4);
      scatter4<<<g, 256>>>(e_pt_src, e_pt_dst, e_tp_src, e_tp_dst,
                           e_pf_src, e_pf_dst, e_fp_src, e_fp_dst,
                           rp_pt, rp_tp, rp_pf, rp_fp, cnt,
                           cs_pt, cs_tp, cs_pf, cs_fp); }

    // score vectors; embed; layer-0 score dots (buffer 0)
    vec_all<<<10, 256>>>(W_src, a_src, W_dst, a_dst, wsv, wdv);
    dot4<<<(NTC * 32) / 256, 256>>>(torque_x, NTC,
         wsv + 1 * 64, ss_tp, wdv + 0 * 64, sd_pt, nullptr, nullptr, nullptr, nullptr);
    dot4<<<(NFC * 32) / 256, 256>>>(force_x, NFC,
         wsv + 3 * 64, ss_fp, wdv + 2 * 64, sd_pf, nullptr, nullptr, nullptr, nullptr);
    embed_k<<<(NPC * 64) / 256, 256>>>(mass, pstate, embW, embS, xp);
    dot4<<<(NPC * 32) / 256, 256>>>(xp, NPC,
         wsv + 0 * 64, ss_pt, wsv + 2 * 64, ss_pf,
         wdv + 1 * 64, sd_tp, wdv + 3 * 64, sd_fp);

    for (int l = 0; l < 5; l++) {
        const float* xti = (l == 0) ? torque_x : xt;
        const float* xfi = (l == 0) ? force_x  : xf;
        const float* Wl = W_src + (size_t)l * 4 * 4096;
        const float* bl = b_conv + (size_t)l * 4 * 64;
        int relu = (l < 3) ? 1 : 0;
        int actor = (l == 4);
        const float* nwsv = wsv + (size_t)(l + 1) * 4 * 64;
        const float* nwdv = wdv + (size_t)(l + 1) * 4 * 64;
        int ci = l & 1, ni = (l + 1) & 1;
        const float* c_ss_pt = ss_pt + ci * NPC;  float* n_ss_pt = ss_pt + ni * NPC;
        const float* c_ss_pf = ss_pf + ci * NPC;  float* n_ss_pf = ss_pf + ni * NPC;
        const float* c_sd_tp = sd_tp + ci * NPC;  float* n_sd_tp = sd_tp + ni * NPC;
        const float* c_sd_fp = sd_fp + ci * NPC;  float* n_sd_fp = sd_fp + ni * NPC;
        const float* c_ss_tp = ss_tp + ci * NTC;  float* n_ss_tp = ss_tp + ni * NTC;
        const float* c_sd_pt = sd_pt + ci * NTC;  float* n_sd_pt = sd_pt + ni * NTC;
        const float* c_ss_fp = ss_fp + ci * NFC;  float* n_ss_fp = ss_fp + ni * NFC;
        const float* c_sd_pf = sd_pf + ci * NFC;  float* n_sd_pf = sd_pf + ni * NFC;

        if (!actor) {
            // 1) transform-first for t/f dst (reads xp BEFORE gat_p overwrites it)
            mm_hs<<<2 * (NPC / 64), 256>>>(xp, Wl + 0 * 4096, hs0, Wl + 2 * 4096, hs1);
            // 2) p-dst: consumes OLD xt/xf, writes new xp
            gat_p<<<NPC / 64, 256>>>(
                rp_tp, cs_tp, c_ss_tp, c_sd_tp, xti, Wl + 1 * 4096,
                rp_fp, cs_fp, c_ss_fp, c_sd_fp, xfi, Wl + 3 * 4096,
                bl + 1 * 64, bl + 3 * 64,
                xp, relu,
                nwsv + 0 * 64, n_ss_pt, nwsv + 2 * 64, n_ss_pf,
                nwdv + 1 * 64, n_sd_tp, nwdv + 3 * 64, n_sd_fp);
            // 3) t/f-dst: overwrites xt/xf IN PLACE (old values already consumed)
            agg_tf<<<NTC / 128 + NFC / 128, 512>>>(NTC / 128,
                rp_pt, cs_pt, c_ss_pt, c_sd_pt, hs0, bl + 0 * 64, xt,
                nwsv + 1 * 64, n_ss_tp, nwdv + 0 * 64, n_sd_pt,
                rp_pf, cs_pf, c_ss_pf, c_sd_pf, hs1, bl + 2 * 64, xf,
                nwsv + 3 * 64, n_ss_fp, nwdv + 2 * 64, n_sd_pf,
                relu);
        } else {
            gat_p<<<NPC / 64, 256>>>(
                rp_tp, cs_tp, c_ss_tp, c_sd_tp, xti, Wl + 1 * 4096,
                rp_fp, cs_fp, c_ss_fp, c_sd_fp, xfi, Wl + 3 * 4096,
                bl + 1 * 64, bl + 3 * 64,
                ap, 0,
                nullptr, nullptr, nullptr, nullptr,
                nullptr, nullptr, nullptr, nullptr);
        }
    }

    // pooling over final x (single buffers)
    pool_k<<<BC, 256>>>(xp, 64, rep, 0);
    pool_k<<<BC, 256>>>(xt, 512, rep, 192);
    pool_k<<<BC, 256>>>(xf, 512, rep, 384);

    // actor head
    ln_ra<<<(NPC * 32) / 256, 256>>>(ap, ln_g, ln_b, outaW, outab, ra);
    act_softmax<<<BC, 64>>>(ra, part_id, out);

    // value head
    mlp_k<<<BC, 64>>>(rep, 576, innW, innb, h1);
    mlp_k<<<BC, 64>>>(h1, 64, fulW, fulb, h2);
    mlp_out<<<(BC * 32) / 256, 256>>>(h2, outW, outb, out + BC * 128);
}

// round 12
// speedup vs baseline: 1.2949x; 1.2077x over previous
#include <cuda_runtime.h>
#include <math.h>

#define NPC 16384
#define NTC 131072
#define NFC 131072
#define EC  262144
#define BC  256
#define FULLMASK 0xffffffffu

// ---------------- device scratch ----------------
__device__ float g_xp[NPC * 64];
__device__ float g_xt[NTC * 64];        // single-buffered: gat_p reads before agg_tf overwrites
__device__ float g_xf[NFC * 64];
__device__ float g_ap[NPC * 64];
__device__ float g_hs0[NPC * 64];       // xp @ W[pt]
__device__ float g_hs1[NPC * 64];       // xp @ W[pf]
__device__ float g_ss_pt[2][NPC], g_ss_pf[2][NPC], g_sd_tp[2][NPC], g_sd_fp[2][NPC];
__device__ float g_ss_tp[2][NTC], g_sd_pt[2][NTC];
__device__ float g_ss_fp[2][NFC], g_sd_pf[2][NFC];
__device__ float g_wsv[5 * 4 * 64], g_wdv[5 * 4 * 64];
__device__ int g_rp_pt[NTC + 1], g_rp_pf[NFC + 1];
__device__ int g_rp_tp[NPC + 1], g_rp_fp[NPC + 1];
__device__ int g_cs_pt[EC], g_cs_tp[EC], g_cs_pf[EC], g_cs_fp[EC];
__device__ int g_cnt[4 * NTC];
__device__ int g_aux[520];              // 4*128 block sums + 4 totals
__device__ float g_ra[NPC * 2];
__device__ float g_rep[BC * 576];
__device__ float g_h1[BC * 64], g_h2[BC * 64];

// ---------------- batched CSR build ----------------
__global__ void zero4(int* c) {
    int i = blockIdx.x * blockDim.x + threadIdx.x;
    if (i < 4 * NTC) c[i] = 0;
}

__global__ void hist4(const int* __restrict__ d0, const int* __restrict__ d1,
                      const int* __restrict__ d2, const int* __restrict__ d3,
                      int* __restrict__ cnt) {
    int t = blockIdx.y;
    const int* d = (t == 0) ? d0 : (t == 1) ? d1 : (t == 2) ? d2 : d3;
    int* c = cnt + t * NTC;
    int i = blockIdx.x * blockDim.x + threadIdx.x;
    if (i < EC) atomicAdd(&c[d[i]], 1);
}

// phase A: per-1024-block local exclusive scan; block totals -> aux
__global__ void __launch_bounds__(1024) scanA(const int* __restrict__ cnt,
        int* rp0, int* rp1, int* rp2, int* rp3, int* __restrict__ aux) {
    __shared__ int ws[32];
    int t = blockIdx.y;
    int* rowptr = (t == 0) ? rp0 : (t == 1) ? rp1 : (t == 2) ? rp2 : rp3;
    int n = (t == 0) ? NTC : (t == 1) ? NPC : (t == 2) ? NFC : NPC;
    const int* deg = cnt + t * NTC;
    int tid = threadIdx.x, lane = tid & 31, wid = tid >> 5;
    int i = blockIdx.x * 1024 + tid;
    int v = (i < n) ? deg[i] : 0;
    int x = v;
    #pragma unroll
    for (int off = 1; off < 32; off <<= 1) {
        int y = __shfl_up_sync(FULLMASK, x, off);
        if (lane >= off) x += y;
    }
    if (lane == 31) ws[wid] = x;
    __syncthreads();
    if (tid < 32) {
        int s = ws[tid];
        #pragma unroll
        for (int off = 1; off < 32; off <<= 1) {
            int y = __shfl_up_sync(FULLMASK, s, off);
            if (tid >= off) s += y;
        }
        ws[tid] = s;
    }
    __syncthreads();
    int excl = x - v + (wid ? ws[wid - 1] : 0);
    if (i < n) rowptr[i] = excl;
    if (tid == 0) aux[t * 128 + blockIdx.x] = ws[31];
}

// phase B: scan the 4x128 block sums (1 block, 512 threads)
__global__ void __launch_bounds__(512) scanB(int* __restrict__ aux) {
    __shared__ int wsum[16];
    int tid = threadIdx.x;
    int t = tid >> 7, idx = tid & 127;
    int lane = tid & 31, wid = tid >> 5;
    int v = aux[t * 128 + idx];
    int x = v;
    #pragma unroll
    for (int off = 1; off < 32; off <<= 1) {
        int y = __shfl_up_sync(FULLMASK, x, off);
        if (lane >= off) x += y;
    }
    if (lane == 31) wsum[wid] = x;
    __syncthreads();
    int offsum = 0;
    for (int w = t * 4; w < wid; w++) offsum += wsum[w];
    int excl = x - v + offsum;
    aux[t * 128 + idx] = excl;
    if (idx == 127) aux[512 + t] = excl + v;
}

// phase C: add block offsets, re-zero cnt, write rowptr[n]
__global__ void __launch_bounds__(1024) scanC(int* __restrict__ cnt,
        int* rp0, int* rp1, int* rp2, int* rp3, const int* __restrict__ aux) {
    int t = blockIdx.y;
    int* rowptr = (t == 0) ? rp0 : (t == 1) ? rp1 : (t == 2) ? rp2 : rp3;
    int n = (t == 0) ? NTC : (t == 1) ? NPC : (t == 2) ? NFC : NPC;
    int i = blockIdx.x * 1024 + threadIdx.x;
    if (i < n) {
        rowptr[i] += aux[t * 128 + blockIdx.x];
        cnt[t * NTC + i] = 0;
    }
    if (i == 0) rowptr[n] = aux[512 + t];
}

__global__ void scatter4(const int* __restrict__ s0, const int* __restrict__ d0,
                         const int* __restrict__ s1, const int* __restrict__ d1,
                         const int* __restrict__ s2, const int* __restrict__ d2,
                         const int* __restrict__ s3, const int* __restrict__ d3,
                         const int* rp0, const int* rp1, const int* rp2, const int* rp3,
                         int* __restrict__ cnt,
                         int* c0, int* c1, int* c2, int* c3) {
    int t = blockIdx.y;
    const int* src = (t == 0) ? s0 : (t == 1) ? s1 : (t == 2) ? s2 : s3;
    const int* dst = (t == 0) ? d0 : (t == 1) ? d1 : (t == 2) ? d2 : d3;
    const int* rp  = (t == 0) ? rp0 : (t == 1) ? rp1 : (t == 2) ? rp2 : rp3;
    int* csr = (t == 0) ? c0 : (t == 1) ? c1 : (t == 2) ? c2 : c3;
    int* cur = cnt + t * NTC;
    int i = blockIdx.x * blockDim.x + threadIdx.x;
    if (i >= EC) return;
    int d = dst[i];
    int pos = rp[d] + atomicAdd(&cur[d], 1);
    csr[pos] = src[i];
}

// ---------------- score vectors for ALL layers ----------------
__global__ void vec_all(const float* __restrict__ Ws, const float* __restrict__ as,
                        const float* __restrict__ Wd, const float* __restrict__ ad,
                        float* __restrict__ wsv, float* __restrict__ wdv) {
    int idx = blockIdx.x * blockDim.x + threadIdx.x;
    if (idx >= 2 * 5 * 4 * 64) return;
    int which = idx >= 1280;
    int r = which ? idx - 1280 : idx;
    int i = r & 63, lt = r >> 6;
    const float* W = which ? Wd : Ws;
    const float* a = which ? ad : as;
    float* o = which ? wdv : wsv;
    float acc = 0.f;
    const float* wr = W + (size_t)(lt * 64 + i) * 64;
    const float* ar = a + lt * 64;
    #pragma unroll 8
    for (int j = 0; j < 64; j++) acc = fmaf(wr[j], ar[j], acc);
    o[r] = acc;
}

// ---------------- embed ----------------
__global__ void embed_k(const float* __restrict__ mass, const int* __restrict__ pstate,
                        const float* __restrict__ embW, const float* __restrict__ embS,
                        float* __restrict__ xp) {
    int idx = blockIdx.x * blockDim.x + threadIdx.x;
    if (idx >= NPC * 64) return;
    int n = idx >> 6, j = idx & 63;
    float v;
    if (j < 32) v = mass[n] * embW[j];
    else {
        int st = pstate[2 * n] + 2 * pstate[2 * n + 1];
        v = embS[st * 32 + (j - 32)];
    }
    xp[idx] = v;
}

// ---------------- up to 4 per-row dot products (layer-0 init) ----------------
__global__ void dot4(const float* __restrict__ X, int n,
                     const float* v0, float* o0, const float* v1, float* o1,
                     const float* v2, float* o2, const float* v3, float* o3) {
    int idx = blockIdx.x * blockDim.x + threadIdx.x;
    int w = idx >> 5;
    if (w >= n) return;
    int lane = idx & 31;
    float2 x = *(const float2*)&X[(size_t)w * 64 + lane * 2];
#define DODOT(v, o) if (v) { \
        float s = x.x * v[2 * lane] + x.y * v[2 * lane + 1]; \
        for (int off = 16; off; off >>= 1) s += __shfl_xor_sync(FULLMASK, s, off); \
        if (lane == 0) o[w] = s; }
    DODOT(v0, o0)
    DODOT(v1, o1)
    DODOT(v2, o2)
    DODOT(v3, o3)
#undef DODOT
}

// ---------------- hs matmul: hs0 = X@W0, hs1 = X@W1 (blockIdx split) ----------------
__global__ void __launch_bounds__(256) mm_hs(const float* __restrict__ X,
                                             const float* __restrict__ W0, float* __restrict__ Y0,
                                             const float* __restrict__ W1, float* __restrict__ Y1) {
    __shared__ float Xs[64][65];
    __shared__ float Wsh[64][68];
    int half = blockIdx.x >= (NPC / 64);
    int row0 = (half ? blockIdx.x - NPC / 64 : blockIdx.x) * 64;
    const float* W = half ? W1 : W0;
    float* Y = half ? Y1 : Y0;
    int tid = threadIdx.x;
    const float4* W4 = (const float4*)W;
    for (int i = tid; i < 1024; i += 256) {
        float4 v = W4[i];
        int r = i >> 4, c = (i & 15) * 4;
        Wsh[r][c] = v.x; Wsh[r][c + 1] = v.y; Wsh[r][c + 2] = v.z; Wsh[r][c + 3] = v.w;
    }
    const float4* X4 = (const float4*)(X + (size_t)row0 * 64);
    for (int i = tid; i < 1024; i += 256) {
        float4 v = X4[i];
        int r = i >> 4, c = (i & 15) * 4;
        Xs[r][c] = v.x; Xs[r][c + 1] = v.y; Xs[r][c + 2] = v.z; Xs[r][c + 3] = v.w;
    }
    __syncthreads();
    int tx = tid & 15, ty = tid >> 4;
    int c0 = tx * 4, r0 = ty * 4;
    float acc[4][4] = {};
    #pragma unroll
    for (int k = 0; k < 64; k++) {
        float4 w = *(const float4*)&Wsh[k][c0];
        float x0 = Xs[r0][k], x1 = Xs[r0 + 1][k], x2 = Xs[r0 + 2][k], x3 = Xs[r0 + 3][k];
        acc[0][0] = fmaf(x0, w.x, acc[0][0]); acc[0][1] = fmaf(x0, w.y, acc[0][1]);
        acc[0][2] = fmaf(x0, w.z, acc[0][2]); acc[0][3] = fmaf(x0, w.w, acc[0][3]);
        acc[1][0] = fmaf(x1, w.x, acc[1][0]); acc[1][1] = fmaf(x1, w.y, acc[1][1]);
        acc[1][2] = fmaf(x1, w.z, acc[1][2]); acc[1][3] = fmaf(x1, w.w, acc[1][3]);
        acc[2][0] = fmaf(x2, w.x, acc[2][0]); acc[2][1] = fmaf(x2, w.y, acc[2][1]);
        acc[2][2] = fmaf(x2, w.z, acc[2][2]); acc[2][3] = fmaf(x2, w.w, acc[2][3]);
        acc[3][0] = fmaf(x3, w.x, acc[3][0]); acc[3][1] = fmaf(x3, w.y, acc[3][1]);
        acc[3][2] = fmaf(x3, w.z, acc[3][2]); acc[3][3] = fmaf(x3, w.w, acc[3][3]);
    }
    #pragma unroll
    for (int i = 0; i < 4; i++)
        *(float4*)&Y[((size_t)(row0 + r0 + i)) * 64 + c0] =
            make_float4(acc[i][0], acc[i][1], acc[i][2], acc[i][3]);
}

// ---------------- t/f aggregation: 4-lane groups, two-pass fixed-max ----------------
__global__ void __launch_bounds__(512) agg_tf(int nA,
        const int* rpA, const int* csA, const float* ssA, const float* sdA,
        const float* hsA, const float* bA, float* YA,
        const float* vA0, float* oA0, const float* vA1, float* oA1,
        const int* rpB, const int* csB, const float* ssB, const float* sdB,
        const float* hsB, const float* bB, float* YB,
        const float* vB0, float* oB0, const float* vB1, float* oB1,
        int relu) {
    bool isA = (int)blockIdx.x < nA;
    int row0 = (isA ? blockIdx.x : blockIdx.x - nA) * 128;
    const int* rp = isA ? rpA : rpB;
    const int* cs = isA ? csA : csB;
    const float* ss = isA ? ssA : ssB;
    const float* sd = isA ? sdA : sdB;
    const float* hs = isA ? hsA : hsB;
    const float* b = isA ? bA : bB;
    float* Y = isA ? YA : YB;
    const float* v0 = isA ? vA0 : vB0;  float* o0 = isA ? oA0 : oB0;
    const float* v1 = isA ? vA1 : vB1;  float* o1 = isA ? oA1 : oB1;

    int tid = threadIdx.x;
    int g = tid >> 2, gl = tid & 3;
    int d = row0 + g;
    int beg = rp[d], end = rp[d + 1];
    float sdv = sd[d];
    float m = -1e30f;
    for (int j = beg + gl; j < end; j += 4) {
        float t = ss[cs[j]] + sdv;
        t = t > 0.f ? t : 0.2f * t;
        m = fmaxf(m, t);
    }
    m = fmaxf(m, __shfl_xor_sync(FULLMASK, m, 1));
    m = fmaxf(m, __shfl_xor_sync(FULLMASK, m, 2));
    float s = 0.f;
    float4 a0 = {0,0,0,0}, a1 = {0,0,0,0}, a2 = {0,0,0,0}, a3 = {0,0,0,0};
    const float4* H4 = (const float4*)hs;
    #pragma unroll 2
    for (int j = beg; j < end; j++) {
        int src = cs[j];
        float t = ss[src] + sdv;
        t = t > 0.f ? t : 0.2f * t;
        float ex = __expf(t - m);
        s += ex;
        size_t hb = (size_t)src * 16 + gl * 4;
        float4 h0 = H4[hb], h1 = H4[hb + 1], h2 = H4[hb + 2], h3 = H4[hb + 3];
        a0.x = fmaf(ex, h0.x, a0.x); a0.y = fmaf(ex, h0.y, a0.y);
        a0.z = fmaf(ex, h0.z, a0.z); a0.w = fmaf(ex, h0.w, a0.w);
        a1.x = fmaf(ex, h1.x, a1.x); a1.y = fmaf(ex, h1.y, a1.y);
        a1.z = fmaf(ex, h1.z, a1.z); a1.w = fmaf(ex, h1.w, a1.w);
        a2.x = fmaf(ex, h2.x, a2.x); a2.y = fmaf(ex, h2.y, a2.y);
        a2.z = fmaf(ex, h2.z, a2.z); a2.w = fmaf(ex, h2.w, a2.w);
        a3.x = fmaf(ex, h3.x, a3.x); a3.y = fmaf(ex, h3.y, a3.y);
        a3.z = fmaf(ex, h3.z, a3.z); a3.w = fmaf(ex, h3.w, a3.w);
    }
    float inv = s > 0.f ? 1.f / s : 0.f;
    const float4* B4 = (const float4*)b;
    float4 bb0 = B4[gl * 4], bb1 = B4[gl * 4 + 1], bb2 = B4[gl * 4 + 2], bb3 = B4[gl * 4 + 3];
    float4 ot[4];
    ot[0] = make_float4(a0.x * inv + bb0.x, a0.y * inv + bb0.y, a0.z * inv + bb0.z, a0.w * inv + bb0.w);
    ot[1] = make_float4(a1.x * inv + bb1.x, a1.y * inv + bb1.y, a1.z * inv + bb1.z, a1.w * inv + bb1.w);
    ot[2] = make_float4(a2.x * inv + bb2.x, a2.y * inv + bb2.y, a2.z * inv + bb2.z, a2.w * inv + bb2.w);
    ot[3] = make_float4(a3.x * inv + bb3.x, a3.y * inv + bb3.y, a3.z * inv + bb3.z, a3.w * inv + bb3.w);
    if (relu) {
        #pragma unroll
        for (int q = 0; q < 4; q++) {
            ot[q].x = fmaxf(ot[q].x, 0.f); ot[q].y = fmaxf(ot[q].y, 0.f);
            ot[q].z = fmaxf(ot[q].z, 0.f); ot[q].w = fmaxf(ot[q].w, 0.f);
        }
    }
    float4* Yr = (float4*)&Y[(size_t)d * 64];
    #pragma unroll
    for (int q = 0; q < 4; q++) Yr[gl * 4 + q] = ot[q];
#define DOT(v, o) { \
        const float4* V4 = (const float4*)v; \
        float dd = 0.f; \
        _Pragma("unroll") \
        for (int q = 0; q < 4; q++) { \
            float4 vv = V4[gl * 4 + q]; \
            dd += ot[q].x * vv.x + ot[q].y * vv.y + ot[q].z * vv.z + ot[q].w * vv.w; \
        } \
        dd += __shfl_xor_sync(FULLMASK, dd, 1); \
        dd += __shfl_xor_sync(FULLMASK, dd, 2); \
        if (gl == 0) o[d] = dd; }
    DOT(v0, o0)
    DOT(v1, o1)
#undef DOT
}

// ---------------- p-dst: 8 lanes/row (2 subgroups split edges), 512 threads ----------------
__global__ void __launch_bounds__(512) gat_p(
        const int* rp1, const int* cs1, const float* ss1, const float* sd1,
        const float* X1, const float* W1,
        const int* rp2, const int* cs2, const float* ss2, const float* sd2,
        const float* X2, const float* W2,
        const float* b1, const float* b2,
        float* __restrict__ Y, int relu,
        const float* v0, float* o0, const float* v1, float* o1,
        const float* v2, float* o2, const float* v3, float* o3) {
    __shared__ float Zs[64 * 68];
    __shared__ float Wsh[64][68];
    int row0 = blockIdx.x * 64;
    int tid = threadIdx.x;
    int g8 = tid >> 3, l8 = tid & 7;       // 64 rows, 8 lanes per row
    int gl = l8 & 3, sg = l8 >> 2;         // col-slice, edge-subgroup
    int tx = tid & 15, ty = tid >> 4;      // matmul: 16x32, 2 rows per thread
    int c0 = tx * 4, r0 = ty * 2;
    float acc[2][4] = {};
    int d = row0 + g8;
    for (int p = 0; p < 2; p++) {
        const int* rp = p ? rp2 : rp1;
        const int* cs = p ? cs2 : cs1;
        const float* ss = p ? ss2 : ss1;
        const float* sd = p ? sd2 : sd1;
        const float* X = p ? X2 : X1;
        const float* W = p ? W2 : W1;
        const float4* W4 = (const float4*)W;
        for (int i = tid; i < 1024; i += 512) {
            float4 v = W4[i];
            int r = i >> 4, c = (i & 15) * 4;
            Wsh[r][c] = v.x; Wsh[r][c + 1] = v.y; Wsh[r][c + 2] = v.z; Wsh[r][c + 3] = v.w;
        }
        int beg = rp[d], end = rp[d + 1];
        float sdv = sd[d];
        // pass 1: max over edges, 8-way strided
        float m = -1e30f;
        for (int j = beg + l8; j < end; j += 8) {
            float t = ss[cs[j]] + sdv;
            t = t > 0.f ? t : 0.2f * t;
            m = fmaxf(m, t);
        }
        m = fmaxf(m, __shfl_xor_sync(FULLMASK, m, 1));
        m = fmaxf(m, __shfl_xor_sync(FULLMASK, m, 2));
        m = fmaxf(m, __shfl_xor_sync(FULLMASK, m, 4));
        // pass 2: subgroup sg takes edges beg+sg, beg+sg+2, ...
        float s = 0.f;
        float4 a0 = {0,0,0,0}, a1 = {0,0,0,0}, a2 = {0,0,0,0}, a3 = {0,0,0,0};
        const float4* H4 = (const float4*)X;
        #pragma unroll 2
        for (int j = beg + sg; j < end; j += 2) {
            int src = cs[j];
            float t = ss[src] + sdv;
            t = t > 0.f ? t : 0.2f * t;
            float ex = __expf(t - m);
            s += ex;
            size_t hb = (size_t)src * 16 + gl * 4;
            float4 h0 = H4[hb], h1 = H4[hb + 1], h2 = H4[hb + 2], h3 = H4[hb + 3];
            a0.x = fmaf(ex, h0.x, a0.x); a0.y = fmaf(ex, h0.y, a0.y);
            a0.z = fmaf(ex, h0.z, a0.z); a0.w = fmaf(ex, h0.w, a0.w);
            a1.x = fmaf(ex, h1.x, a1.x); a1.y = fmaf(ex, h1.y, a1.y);
            a1.z = fmaf(ex, h1.z, a1.z); a1.w = fmaf(ex, h1.w, a1.w);
            a2.x = fmaf(ex, h2.x, a2.x); a2.y = fmaf(ex, h2.y, a2.y);
            a2.z = fmaf(ex, h2.z, a2.z); a2.w = fmaf(ex, h2.w, a2.w);
            a3.x = fmaf(ex, h3.x, a3.x); a3.y = fmaf(ex, h3.y, a3.y);
            a3.z = fmaf(ex, h3.z, a3.z); a3.w = fmaf(ex, h3.w, a3.w);
        }
        // merge the two edge-subgroups (partner lane has same col-slice)
        s += __shfl_xor_sync(FULLMASK, s, 4);
        a0.x += __shfl_xor_sync(FULLMASK, a0.x, 4); a0.y += __shfl_xor_sync(FULLMASK, a0.y, 4);
        a0.z += __shfl_xor_sync(FULLMASK, a0.z, 4); a0.w += __shfl_xor_sync(FULLMASK, a0.w, 4);
        a1.x += __shfl_xor_sync(FULLMASK, a1.x, 4); a1.y += __shfl_xor_sync(FULLMASK, a1.y, 4);
        a1.z += __shfl_xor_sync(FULLMASK, a1.z, 4); a1.w += __shfl_xor_sync(FULLMASK, a1.w, 4);
        a2.x += __shfl_xor_sync(FULLMASK, a2.x, 4); a2.y += __shfl_xor_sync(FULLMASK, a2.y, 4);
        a2.z += __shfl_xor_sync(FULLMASK, a2.z, 4); a2.w += __shfl_xor_sync(FULLMASK, a2.w, 4);
        a3.x += __shfl_xor_sync(FULLMASK, a3.x, 4); a3.y += __shfl_xor_sync(FULLMASK, a3.y, 4);
        a3.z += __shfl_xor_sync(FULLMASK, a3.z, 4); a3.w += __shfl_xor_sync(FULLMASK, a3.w, 4);
        float inv = s > 0.f ? 1.f / s : 0.f;
        if (sg == 0) {
            float4* Zr = (float4*)&Zs[g8 * 68];
            Zr[gl * 4]     = make_float4(a0.x * inv, a0.y * inv, a0.z * inv, a0.w * inv);
            Zr[gl * 4 + 1] = make_float4(a1.x * inv, a1.y * inv, a1.z * inv, a1.w * inv);
            Zr[gl * 4 + 2] = make_float4(a2.x * inv, a2.y * inv, a2.z * inv, a2.w * inv);
            Zr[gl * 4 + 3] = make_float4(a3.x * inv, a3.y * inv, a3.z * inv, a3.w * inv);
        }
        __syncthreads();
        #pragma unroll
        for (int k = 0; k < 64; k++) {
            float4 wv = *(const float4*)&Wsh[k][c0];
            float x0 = Zs[r0 * 68 + k], x1 = Zs[(r0 + 1) * 68 + k];
            acc[0][0] = fmaf(x0, wv.x, acc[0][0]); acc[0][1] = fmaf(x0, wv.y, acc[0][1]);
            acc[0][2] = fmaf(x0, wv.z, acc[0][2]); acc[0][3] = fmaf(x0, wv.w, acc[0][3]);
            acc[1][0] = fmaf(x1, wv.x, acc[1][0]); acc[1][1] = fmaf(x1, wv.y, acc[1][1]);
            acc[1][2] = fmaf(x1, wv.z, acc[1][2]); acc[1][3] = fmaf(x1, wv.w, acc[1][3]);
        }
        __syncthreads();
    }
    // bias + relu, stage to Zs
    #pragma unroll
    for (int i = 0; i < 2; i++)
        #pragma unroll
        for (int c = 0; c < 4; c++) {
            float v = acc[i][c] + b1[c0 + c] + b2[c0 + c];
            if (relu) v = fmaxf(v, 0.f);
            Zs[(r0 + i) * 68 + c0 + c] = v;
        }
    __syncthreads();
    // output: 8-lane group per row, 2 float4 per lane
    float4 ot[2];
    const float4* Zr = (const float4*)&Zs[g8 * 68];
    ot[0] = Zr[l8 * 2]; ot[1] = Zr[l8 * 2 + 1];
    float4* Yr = (float4*)&Y[(size_t)d * 64];
    Yr[l8 * 2] = ot[0]; Yr[l8 * 2 + 1] = ot[1];
#define DOT(v, o) if (v) { \
        const float4* V4 = (const float4*)v; \
        float4 vv0 = V4[l8 * 2], vv1 = V4[l8 * 2 + 1]; \
        float dd = ot[0].x * vv0.x + ot[0].y * vv0.y + ot[0].z * vv0.z + ot[0].w * vv0.w \
                 + ot[1].x * vv1.x + ot[1].y * vv1.y + ot[1].z * vv1.z + ot[1].w * vv1.w; \
        dd += __shfl_xor_sync(FULLMASK, dd, 1); \
        dd += __shfl_xor_sync(FULLMASK, dd, 2); \
        dd += __shfl_xor_sync(FULLMASK, dd, 4); \
        if (l8 == 0) o[d] = dd; }
    DOT(v0, o0)
    DOT(v1, o1)
    DOT(v2, o2)
    DOT(v3, o3)
#undef DOT
}

// ---------------- pooling ----------------
__global__ void pool_k(const float* __restrict__ x, int npg, float* __restrict__ rep, int off) {
    int b = blockIdx.x;
    int t = threadIdx.x;            // 256
    int d = t & 63, c = t >> 6;
    const float* base = x + (size_t)b * npg * 64;
    float mx = -1e30f, mn = 1e30f, sm = 0.f;
    for (int n = c; n < npg; n += 4) {
        float v = base[(size_t)n * 64 + d];
        mx = fmaxf(mx, v); mn = fminf(mn, v); sm += v;
    }
    __shared__ float smx[4][64], smn[4][64], ssm[4][64];
    smx[c][d] = mx; smn[c][d] = mn; ssm[c][d] = sm;
    __syncthreads();
    if (c == 0) {
        for (int i = 1; i < 4; i++) {
            mx = fmaxf(mx, smx[i][d]); mn = fminf(mn, smn[i][d]); sm += ssm[i][d];
        }
        rep[b * 576 + off + d] = mx;
        rep[b * 576 + off + 64 + d] = mn;
        rep[b * 576 + off + 128 + d] = sm / (float)npg;
    }
}

// ---------------- LayerNorm + out_a projection ----------------
__global__ void ln_ra(const float* __restrict__ ap, const float* __restrict__ g,
                      const float* __restrict__ be, const float* __restrict__ Wa,
                      const float* __restrict__ ba, float* __restrict__ ra) {
    int idx = blockIdx.x * blockDim.x + threadIdx.x;
    int n = idx >> 5;
    if (n >= NPC) return;
    int lane = idx & 31;
    float2 v = *(const float2*)&ap[(size_t)n * 64 + lane * 2];
    float sum = v.x + v.y;
    for (int o = 16; o; o >>= 1) sum += __shfl_xor_sync(FULLMASK, sum, o);
    float mu = sum * (1.f / 64.f);
    float dx = v.x - mu, dy = v.y - mu;
    float vs = dx * dx + dy * dy;
    for (int o = 16; o; o >>= 1) vs += __shfl_xor_sync(FULLMASK, vs, o);
    float rs = rsqrtf(vs * (1.f / 64.f) + 1e-5f);
    float y0 = dx * rs * g[2 * lane] + be[2 * lane];
    float y1 = dy * rs * g[2 * lane + 1] + be[2 * lane + 1];
    float r0 = y0 * Wa[(2 * lane) * 2]     + y1 * Wa[(2 * lane + 1) * 2];
    float r1 = y0 * Wa[(2 * lane) * 2 + 1] + y1 * Wa[(2 * lane + 1) * 2 + 1];
    for (int o = 16; o; o >>= 1) r0 += __shfl_xor_sync(FULLMASK, r0, o);
    for (int o = 16; o; o >>= 1) r1 += __shfl_xor_sync(FULLMASK, r1, o);
    if (lane == 0) {
        ra[2 * n]     = r0 + ba[0];
        ra[2 * n + 1] = r1 + ba[1];
    }
}

// ---------------- per-graph softmax + scatter to actions ----------------
__device__ __forceinline__ float blk64_max(float v, volatile float* sh) {
    for (int o = 16; o; o >>= 1) v = fmaxf(v, __shfl_xor_sync(FULLMASK, v, o));
    if ((threadIdx.x & 31) == 0) sh[threadIdx.x >> 5] = v;
    __syncthreads();
    float r = fmaxf(sh[0], sh[1]);
    __syncthreads();
    return r;
}
__device__ __forceinline__ float blk64_sum(float v, volatile float* sh) {
    for (int o = 16; o; o >>= 1) v += __shfl_xor_sync(FULLMASK, v, o);
    if ((threadIdx.x & 31) == 0) sh[threadIdx.x >> 5] = v;
    __syncthreads();
    float r = sh[0] + sh[1];
    __syncthreads();
    return r;
}

__global__ void act_softmax(const float* __restrict__ ra, const int* __restrict__ part_id,
                            float* __restrict__ out) {
    __shared__ float sh[2];
    int b = blockIdx.x, t = threadIdx.x;        // 64
    int n = b * 64 + t;
    float v0 = ra[2 * n], v1 = ra[2 * n + 1];
    float m0 = blk64_max(v0, sh);
    float m1 = blk64_max(v1, sh);
    float e0 = expf(v0 - m0), e1 = expf(v1 - m1);
    float s0 = blk64_sum(e0, sh);
    float s1 = blk64_sum(e1, sh);
    int p = part_id[n];
    out[b * 128 + p] = e0 / s0;
    out[b * 128 + 64 + p] = e1 / s1;
}

// ---------------- value head MLPs ----------------
__global__ void mlp_k(const float* __restrict__ in, int K, const float* __restrict__ W,
                      const float* __restrict__ bias, float* __restrict__ out) {
    __shared__ float s[576];
    int b = blockIdx.x, j = threadIdx.x;        // 64
    for (int k = j; k < K; k += 64) s[k] = in[b * K + k];
    __syncthreads();
    float acc = bias[j];
    for (int k = 0; k < K; k++) acc = fmaf(s[k], W[k * 64 + j], acc);
    acc = 0.5f * acc * (1.f + erff(acc * 0.70710678118654752f));
    out[b * 64 + j] = acc;
}

__global__ void mlp_out(const float* __restrict__ h, const float* __restrict__ Wo,
                        const float* __restrict__ bo, float* __restrict__ V) {
    int idx = blockIdx.x * blockDim.x + threadIdx.x;
    int b = idx >> 5;
    if (b >= BC) return;
    int lane = idx & 31;
    float2 v = *(const float2*)&h[b * 64 + lane * 2];
    float s = v.x * Wo[2 * lane] + v.y * Wo[2 * lane + 1];
    for (int o = 16; o; o >>= 1) s += __shfl_xor_sync(FULLMASK, s, o);
    if (lane == 0) V[b] = tanhf(s + bo[0]);
}

// ---------------- host ----------------
#define SYMF(p, s) do { void* _q; cudaGetSymbolAddress(&_q, s); p = (float*)_q; } while (0)
#define SYMI(p, s) do { void* _q; cudaGetSymbolAddress(&_q, s); p = (int*)_q; } while (0)

extern "C" void kernel_launch(void* const* d_in, const int* in_sizes, int n_in,
                              void* d_out, int out_size) {
    const float* mass      = (const float*)d_in[0];
    const int*   pstate    = (const int*)d_in[1];
    const float* torque_x  = (const float*)d_in[2];
    const float* force_x   = (const float*)d_in[3];
    const int* e_pt_src = (const int*)d_in[4];
    const int* e_pt_dst = (const int*)d_in[5];
    const int* e_tp_src = (const int*)d_in[6];
    const int* e_tp_dst = (const int*)d_in[7];
    const int* e_pf_src = (const int*)d_in[8];
    const int* e_pf_dst = (const int*)d_in[9];
    const int* e_fp_src = (const int*)d_in[10];
    const int* e_fp_dst = (const int*)d_in[11];
    const int* part_id  = (const int*)d_in[13];
    const float* embW   = (const float*)d_in[14];
    const float* embS   = (const float*)d_in[15];
    const float* W_src  = (const float*)d_in[16];
    const float* W_dst  = (const float*)d_in[17];
    const float* a_src  = (const float*)d_in[18];
    const float* a_dst  = (const float*)d_in[19];
    const float* b_conv = (const float*)d_in[20];
    const float* ln_g   = (const float*)d_in[21];
    const float* ln_b   = (const float*)d_in[22];
    const float* outaW  = (const float*)d_in[23];
    const float* outab  = (const float*)d_in[24];
    const float* innW   = (const float*)d_in[25];
    const float* innb   = (const float*)d_in[26];
    const float* fulW   = (const float*)d_in[27];
    const float* fulb   = (const float*)d_in[28];
    const float* outW   = (const float*)d_in[29];
    const float* outb   = (const float*)d_in[30];
    float* out = (float*)d_out;

    float *xp, *xt, *xf, *ap, *hs0, *hs1;
    float *ss_pt, *ss_pf, *sd_tp, *sd_fp, *ss_tp, *sd_pt, *ss_fp, *sd_pf;
    float *wsv, *wdv, *ra, *rep, *h1, *h2;
    int *rp_pt, *rp_pf, *rp_tp, *rp_fp, *cs_pt, *cs_tp, *cs_pf, *cs_fp, *cnt, *aux;
    SYMF(xp, g_xp); SYMF(xt, g_xt); SYMF(xf, g_xf); SYMF(ap, g_ap);
    SYMF(hs0, g_hs0); SYMF(hs1, g_hs1);
    SYMF(ss_pt, g_ss_pt); SYMF(ss_pf, g_ss_pf); SYMF(sd_tp, g_sd_tp); SYMF(sd_fp, g_sd_fp);
    SYMF(ss_tp, g_ss_tp); SYMF(sd_pt, g_sd_pt); SYMF(ss_fp, g_ss_fp); SYMF(sd_pf, g_sd_pf);
    SYMF(wsv, g_wsv); SYMF(wdv, g_wdv); SYMF(ra, g_ra);
    SYMF(rep, g_rep); SYMF(h1, g_h1); SYMF(h2, g_h2);
    SYMI(rp_pt, g_rp_pt); SYMI(rp_pf, g_rp_pf); SYMI(rp_tp, g_rp_tp); SYMI(rp_fp, g_rp_fp);
    SYMI(cs_pt, g_cs_pt); SYMI(cs_tp, g_cs_tp); SYMI(cs_pf, g_cs_pf); SYMI(cs_fp, g_cs_fp);
    SYMI(cnt, g_cnt); SYMI(aux, g_aux);

    // batched CSR build (parallel 3-phase scan)
    zero4<<<(4 * NTC) / 256, 256>>>(cnt);
    { dim3 g(EC / 256, 4); hist4<<<g, 256>>>(e_pt_dst, e_tp_dst, e_pf_dst, e_fp_dst, cnt); }
    { dim3 g(128, 4); scanA<<<g, 1024>>>(cnt, rp_pt, rp_tp, rp_pf, rp_fp, aux); }
    scanB<<<1, 512>>>(aux);
    { dim3 g(128, 4); scanC<<<g, 1024>>>(cnt, rp_pt, rp_tp, rp_pf, rp_fp, aux); }
    { dim3 g(EC / 256, 4);
      scatter4<<<g, 256>>>(e_pt_src, e_pt_dst, e_tp_src, e_tp_dst,
                           e_pf_src, e_pf_dst, e_fp_src, e_fp_dst,
                           rp_pt, rp_tp, rp_pf, rp_fp, cnt,
                           cs_pt, cs_tp, cs_pf, cs_fp); }

    // score vectors; embed; layer-0 score dots (buffer 0)
    vec_all<<<10, 256>>>(W_src, a_src, W_dst, a_dst, wsv, wdv);
    dot4<<<(NTC * 32) / 256, 256>>>(torque_x, NTC,
         wsv + 1 * 64, ss_tp, wdv + 0 * 64, sd_pt, nullptr, nullptr, nullptr, nullptr);
    dot4<<<(NFC * 32) / 256, 256>>>(force_x, NFC,
         wsv + 3 * 64, ss_fp, wdv + 2 * 64, sd_pf, nullptr, nullptr, nullptr, nullptr);
    embed_k<<<(NPC * 64) / 256, 256>>>(mass, pstate, embW, embS, xp);
    dot4<<<(NPC * 32) / 256, 256>>>(xp, NPC,
         wsv + 0 * 64, ss_pt, wsv + 2 * 64, ss_pf,
         wdv + 1 * 64, sd_tp, wdv + 3 * 64, sd_fp);

    for (int l = 0; l < 5; l++) {
        const float* xti = (l == 0) ? torque_x : xt;
        const float* xfi = (l == 0) ? force_x  : xf;
        const float* Wl = W_src + (size_t)l * 4 * 4096;
        const float* bl = b_conv + (size_t)l * 4 * 64;
        int relu = (l < 3) ? 1 : 0;
        int actor = (l == 4);
        const float* nwsv = wsv + (size_t)(l + 1) * 4 * 64;
        const float* nwdv = wdv + (size_t)(l + 1) * 4 * 64;
        int ci = l & 1, ni = (l + 1) & 1;
        const float* c_ss_pt = ss_pt + ci * NPC;  float* n_ss_pt = ss_pt + ni * NPC;
        const float* c_ss_pf = ss_pf + ci * NPC;  float* n_ss_pf = ss_pf + ni * NPC;
        const float* c_sd_tp = sd_tp + ci * NPC;  float* n_sd_tp = sd_tp + ni * NPC;
        const float* c_sd_fp = sd_fp + ci * NPC;  float* n_sd_fp = sd_fp + ni * NPC;
        const float* c_ss_tp = ss_tp + ci * NTC;  float* n_ss_tp = ss_tp + ni * NTC;
        const float* c_sd_pt = sd_pt + ci * NTC;  float* n_sd_pt = sd_pt + ni * NTC;
        const float* c_ss_fp = ss_fp + ci * NFC;  float* n_ss_fp = ss_fp + ni * NFC;
        const float* c_sd_pf = sd_pf + ci * NFC;  float* n_sd_pf = sd_pf + ni * NFC;

        if (!actor) {
            // 1) transform-first for t/f dst (reads xp BEFORE gat_p overwrites it)
            mm_hs<<<2 * (NPC / 64), 256>>>(xp, Wl + 0 * 4096, hs0, Wl + 2 * 4096, hs1);
            // 2) p-dst: consumes OLD xt/xf, writes new xp
            gat_p<<<NPC / 64, 512>>>(
                rp_tp, cs_tp, c_ss_tp, c_sd_tp, xti, Wl + 1 * 4096,
                rp_fp, cs_fp, c_ss_fp, c_sd_fp, xfi, Wl + 3 * 4096,
                bl + 1 * 64, bl + 3 * 64,
                xp, relu,
                nwsv + 0 * 64, n_ss_pt, nwsv + 2 * 64, n_ss_pf,
                nwdv + 1 * 64, n_sd_tp, nwdv + 3 * 64, n_sd_fp);
            // 3) t/f-dst: overwrites xt/xf IN PLACE (old values already consumed)
            agg_tf<<<NTC / 128 + NFC / 128, 512>>>(NTC / 128,
                rp_pt, cs_pt, c_ss_pt, c_sd_pt, hs0, bl + 0 * 64, xt,
                nwsv + 1 * 64, n_ss_tp, nwdv + 0 * 64, n_sd_pt,
                rp_pf, cs_pf, c_ss_pf, c_sd_pf, hs1, bl + 2 * 64, xf,
                nwsv + 3 * 64, n_ss_fp, nwdv + 2 * 64, n_sd_pf,
                relu);
        } else {
            gat_p<<<NPC / 64, 512>>>(
                rp_tp, cs_tp, c_ss_tp, c_sd_tp, xti, Wl + 1 * 4096,
                rp_fp, cs_fp, c_ss_fp, c_sd_fp, xfi, Wl + 3 * 4096,
                bl + 1 * 64, bl + 3 * 64,
                ap, 0,
                nullptr, nullptr, nullptr, nullptr,
                nullptr, nullptr, nullptr, nullptr);
        }
    }

    // pooling over final x (single buffers)
    pool_k<<<BC, 256>>>(xp, 64, rep, 0);
    pool_k<<<BC, 256>>>(xt, 512, rep, 192);
    pool_k<<<BC, 256>>>(xf, 512, rep, 384);

    // actor head
    ln_ra<<<(NPC * 32) / 256, 256>>>(ap, ln_g, ln_b, outaW, outab, ra);
    act_softmax<<<BC, 64>>>(ra, part_id, out);

    // value head
    mlp_k<<<BC, 64>>>(rep, 576, innW, innb, h1);
    mlp_k<<<BC, 64>>>(h1, 64, fulW, fulb, h2);
    mlp_out<<<(BC * 32) / 256, 256>>>(h2, outW, outb, out + BC * 128);
}

// round 13
// speedup vs baseline: 1.4039x; 1.0842x over previous
#include <cuda_runtime.h>
#include <math.h>

#define NPC 16384
#define NTC 131072
#define NFC 131072
#define EC  262144
#define BC  256
#define FULLMASK 0xffffffffu

// ---------------- device scratch ----------------
__device__ float g_xp[NPC * 64];
__device__ float g_xt[2][NTC * 64];     // double-buffered for intra-layer overlap
__device__ float g_xf[2][NFC * 64];
__device__ float g_ap[NPC * 64];
__device__ float g_hs0[2][NPC * 64];    // xp @ W[pt], parity-buffered
__device__ float g_hs1[2][NPC * 64];    // xp @ W[pf]
__device__ float g_ss_pt[2][NPC], g_ss_pf[2][NPC], g_sd_tp[2][NPC], g_sd_fp[2][NPC];
__device__ float g_ss_tp[2][NTC], g_sd_pt[2][NTC];
__device__ float g_ss_fp[2][NFC], g_sd_pf[2][NFC];
__device__ float g_wsv[5 * 4 * 64], g_wdv[5 * 4 * 64];
__device__ int g_rp_pt[NTC + 1], g_rp_pf[NFC + 1];
__device__ int g_rp_tp[NPC + 1], g_rp_fp[NPC + 1];
__device__ int g_cs_pt[EC], g_cs_tp[EC], g_cs_pf[EC], g_cs_fp[EC];
__device__ int g_cnt[4 * NTC];
__device__ int g_aux[520];
__device__ float g_ra[NPC * 2];
__device__ float g_rep[BC * 576];
__device__ float g_h1[BC * 64], g_h2[BC * 64];

// ---------------- batched CSR build ----------------
__global__ void zero4(int* c) {
    int i = blockIdx.x * blockDim.x + threadIdx.x;
    if (i < 4 * NTC) c[i] = 0;
}

__global__ void hist4(const int* __restrict__ d0, const int* __restrict__ d1,
                      const int* __restrict__ d2, const int* __restrict__ d3,
                      int* __restrict__ cnt) {
    int t = blockIdx.y;
    const int* d = (t == 0) ? d0 : (t == 1) ? d1 : (t == 2) ? d2 : d3;
    int* c = cnt + t * NTC;
    int i = blockIdx.x * blockDim.x + threadIdx.x;
    if (i < EC) atomicAdd(&c[d[i]], 1);
}

__global__ void __launch_bounds__(1024) scanA(const int* __restrict__ cnt,
        int* rp0, int* rp1, int* rp2, int* rp3, int* __restrict__ aux) {
    __shared__ int ws[32];
    int t = blockIdx.y;
    int* rowptr = (t == 0) ? rp0 : (t == 1) ? rp1 : (t == 2) ? rp2 : rp3;
    int n = (t == 0) ? NTC : (t == 1) ? NPC : (t == 2) ? NFC : NPC;
    const int* deg = cnt + t * NTC;
    int tid = threadIdx.x, lane = tid & 31, wid = tid >> 5;
    int i = blockIdx.x * 1024 + tid;
    int v = (i < n) ? deg[i] : 0;
    int x = v;
    #pragma unroll
    for (int off = 1; off < 32; off <<= 1) {
        int y = __shfl_up_sync(FULLMASK, x, off);
        if (lane >= off) x += y;
    }
    if (lane == 31) ws[wid] = x;
    __syncthreads();
    if (tid < 32) {
        int s = ws[tid];
        #pragma unroll
        for (int off = 1; off < 32; off <<= 1) {
            int y = __shfl_up_sync(FULLMASK, s, off);
            if (tid >= off) s += y;
        }
        ws[tid] = s;
    }
    __syncthreads();
    int excl = x - v + (wid ? ws[wid - 1] : 0);
    if (i < n) rowptr[i] = excl;
    if (tid == 0) aux[t * 128 + blockIdx.x] = ws[31];
}

__global__ void __launch_bounds__(512) scanB(int* __restrict__ aux) {
    __shared__ int wsum[16];
    int tid = threadIdx.x;
    int t = tid >> 7, idx = tid & 127;
    int lane = tid & 31, wid = tid >> 5;
    int v = aux[t * 128 + idx];
    int x = v;
    #pragma unroll
    for (int off = 1; off < 32; off <<= 1) {
        int y = __shfl_up_sync(FULLMASK, x, off);
        if (lane >= off) x += y;
    }
    if (lane == 31) wsum[wid] = x;
    __syncthreads();
    int offsum = 0;
    for (int w = t * 4; w < wid; w++) offsum += wsum[w];
    int excl = x - v + offsum;
    aux[t * 128 + idx] = excl;
    if (idx == 127) aux[512 + t] = excl + v;
}

__global__ void __launch_bounds__(1024) scanC(int* __restrict__ cnt,
        int* rp0, int* rp1, int* rp2, int* rp3, const int* __restrict__ aux) {
    int t = blockIdx.y;
    int* rowptr = (t == 0) ? rp0 : (t == 1) ? rp1 : (t == 2) ? rp2 : rp3;
    int n = (t == 0) ? NTC : (t == 1) ? NPC : (t == 2) ? NFC : NPC;
    int i = blockIdx.x * 1024 + threadIdx.x;
    if (i < n) {
        rowptr[i] += aux[t * 128 + blockIdx.x];
        cnt[t * NTC + i] = 0;
    }
    if (i == 0) rowptr[n] = aux[512 + t];
}

__global__ void scatter4(const int* __restrict__ s0, const int* __restrict__ d0,
                         const int* __restrict__ s1, const int* __restrict__ d1,
                         const int* __restrict__ s2, const int* __restrict__ d2,
                         const int* __restrict__ s3, const int* __restrict__ d3,
                         const int* rp0, const int* rp1, const int* rp2, const int* rp3,
                         int* __restrict__ cnt,
                         int* c0, int* c1, int* c2, int* c3) {
    int t = blockIdx.y;
    const int* src = (t == 0) ? s0 : (t == 1) ? s1 : (t == 2) ? s2 : s3;
    const int* dst = (t == 0) ? d0 : (t == 1) ? d1 : (t == 2) ? d2 : d3;
    const int* rp  = (t == 0) ? rp0 : (t == 1) ? rp1 : (t == 2) ? rp2 : rp3;
    int* csr = (t == 0) ? c0 : (t == 1) ? c1 : (t == 2) ? c2 : c3;
    int* cur = cnt + t * NTC;
    int i = blockIdx.x * blockDim.x + threadIdx.x;
    if (i >= EC) return;
    int d = dst[i];
    int pos = rp[d] + atomicAdd(&cur[d], 1);
    csr[pos] = src[i];
}

// ---------------- score vectors for ALL layers ----------------
__global__ void vec_all(const float* __restrict__ Ws, const float* __restrict__ as,
                        const float* __restrict__ Wd, const float* __restrict__ ad,
                        float* __restrict__ wsv, float* __restrict__ wdv) {
    int idx = blockIdx.x * blockDim.x + threadIdx.x;
    if (idx >= 2 * 5 * 4 * 64) return;
    int which = idx >= 1280;
    int r = which ? idx - 1280 : idx;
    int i = r & 63, lt = r >> 6;
    const float* W = which ? Wd : Ws;
    const float* a = which ? ad : as;
    float* o = which ? wdv : wsv;
    float acc = 0.f;
    const float* wr = W + (size_t)(lt * 64 + i) * 64;
    const float* ar = a + lt * 64;
    #pragma unroll 8
    for (int j = 0; j < 64; j++) acc = fmaf(wr[j], ar[j], acc);
    o[r] = acc;
}

// ---------------- embed ----------------
__global__ void embed_k(const float* __restrict__ mass, const int* __restrict__ pstate,
                        const float* __restrict__ embW, const float* __restrict__ embS,
                        float* __restrict__ xp) {
    int idx = blockIdx.x * blockDim.x + threadIdx.x;
    if (idx >= NPC * 64) return;
    int n = idx >> 6, j = idx & 63;
    float v;
    if (j < 32) v = mass[n] * embW[j];
    else {
        int st = pstate[2 * n] + 2 * pstate[2 * n + 1];
        v = embS[st * 32 + (j - 32)];
    }
    xp[idx] = v;
}

// ---------------- up to 4 per-row dot products (layer-0 init) ----------------
__global__ void dot4(const float* __restrict__ X, int n,
                     const float* v0, float* o0, const float* v1, float* o1,
                     const float* v2, float* o2, const float* v3, float* o3) {
    int idx = blockIdx.x * blockDim.x + threadIdx.x;
    int w = idx >> 5;
    if (w >= n) return;
    int lane = idx & 31;
    float2 x = *(const float2*)&X[(size_t)w * 64 + lane * 2];
#define DODOT(v, o) if (v) { \
        float s = x.x * v[2 * lane] + x.y * v[2 * lane + 1]; \
        for (int off = 16; off; off >>= 1) s += __shfl_xor_sync(FULLMASK, s, off); \
        if (lane == 0) o[w] = s; }
    DODOT(v0, o0)
    DODOT(v1, o1)
    DODOT(v2, o2)
    DODOT(v3, o3)
#undef DODOT
}

// ---------------- bootstrap hs matmul ----------------
__global__ void __launch_bounds__(256) mm_hs(const float* __restrict__ X,
                                             const float* __restrict__ W0, float* __restrict__ Y0,
                                             const float* __restrict__ W1, float* __restrict__ Y1) {
    __shared__ float Xs[64][65];
    __shared__ float Wsh[64][68];
    int half = blockIdx.x >= (NPC / 64);
    int row0 = (half ? blockIdx.x - NPC / 64 : blockIdx.x) * 64;
    const float* W = half ? W1 : W0;
    float* Y = half ? Y1 : Y0;
    int tid = threadIdx.x;
    const float4* W4 = (const float4*)W;
    for (int i = tid; i < 1024; i += 256) {
        float4 v = W4[i];
        int r = i >> 4, c = (i & 15) * 4;
        Wsh[r][c] = v.x; Wsh[r][c + 1] = v.y; Wsh[r][c + 2] = v.z; Wsh[r][c + 3] = v.w;
    }
    const float4* X4 = (const float4*)(X + (size_t)row0 * 64);
    for (int i = tid; i < 1024; i += 256) {
        float4 v = X4[i];
        int r = i >> 4, c = (i & 15) * 4;
        Xs[r][c] = v.x; Xs[r][c + 1] = v.y; Xs[r][c + 2] = v.z; Xs[r][c + 3] = v.w;
    }
    __syncthreads();
    int tx = tid & 15, ty = tid >> 4;
    int c0 = tx * 4, r0 = ty * 4;
    float acc[4][4] = {};
    #pragma unroll
    for (int k = 0; k < 64; k++) {
        float4 w = *(const float4*)&Wsh[k][c0];
        float x0 = Xs[r0][k], x1 = Xs[r0 + 1][k], x2 = Xs[r0 + 2][k], x3 = Xs[r0 + 3][k];
        acc[0][0] = fmaf(x0, w.x, acc[0][0]); acc[0][1] = fmaf(x0, w.y, acc[0][1]);
        acc[0][2] = fmaf(x0, w.z, acc[0][2]); acc[0][3] = fmaf(x0, w.w, acc[0][3]);
        acc[1][0] = fmaf(x1, w.x, acc[1][0]); acc[1][1] = fmaf(x1, w.y, acc[1][1]);
        acc[1][2] = fmaf(x1, w.z, acc[1][2]); acc[1][3] = fmaf(x1, w.w, acc[1][3]);
        acc[2][0] = fmaf(x2, w.x, acc[2][0]); acc[2][1] = fmaf(x2, w.y, acc[2][1]);
        acc[2][2] = fmaf(x2, w.z, acc[2][2]); acc[2][3] = fmaf(x2, w.w, acc[2][3]);
        acc[3][0] = fmaf(x3, w.x, acc[3][0]); acc[3][1] = fmaf(x3, w.y, acc[3][1]);
        acc[3][2] = fmaf(x3, w.z, acc[3][2]); acc[3][3] = fmaf(x3, w.w, acc[3][3]);
    }
    #pragma unroll
    for (int i = 0; i < 4; i++)
        *(float4*)&Y[((size_t)(row0 + r0 + i)) * 64 + c0] =
            make_float4(acc[i][0], acc[i][1], acc[i][2], acc[i][3]);
}

// ================== MEGA: p-dst GAT (+hs epilogue) AND t/f aggregation in one launch ==========
__global__ void __launch_bounds__(512, 2) mega(
        int npBlocks, int ntfA,
        // p-part
        const int* rp1, const int* cs1, const float* ss1, const float* sd1,
        const float* X1, const float* W1,
        const int* rp2, const int* cs2, const float* ss2, const float* sd2,
        const float* X2, const float* W2,
        const float* b1, const float* b2, float* Yp, int relu,
        const float* pv0, float* po0, const float* pv1, float* po1,
        const float* pv2, float* po2, const float* pv3, float* po3,
        const float* Wn0, float* hsOut0, const float* Wn1, float* hsOut1,
        // tf-part
        const int* rpA, const int* csA, const float* ssA, const float* sdA,
        const float* hsA, const float* bA, float* YA,
        const float* vA0, float* oA0, const float* vA1, float* oA1,
        const int* rpB, const int* csB, const float* ssB, const float* sdB,
        const float* hsB, const float* bB, float* YB,
        const float* vB0, float* oB0, const float* vB1, float* oB1) {
    __shared__ float Zs[64 * 68];
    __shared__ float Wsh[64][68];
    int tid = threadIdx.x;

    if ((int)blockIdx.x < npBlocks) {
        // ---------------- p-part: 8 lanes/row ----------------
        int row0 = blockIdx.x * 64;
        int g8 = tid >> 3, l8 = tid & 7;
        int gl = l8 & 3, sg = l8 >> 2;
        int tx = tid & 15, ty = tid >> 4;
        int c0 = tx * 4, r0 = ty * 2;
        float acc[2][4] = {};
        int d = row0 + g8;
        for (int p = 0; p < 2; p++) {
            const int* rp = p ? rp2 : rp1;
            const int* cs = p ? cs2 : cs1;
            const float* ss = p ? ss2 : ss1;
            const float* sd = p ? sd2 : sd1;
            const float* X = p ? X2 : X1;
            const float* W = p ? W2 : W1;
            const float4* W4 = (const float4*)W;
            for (int i = tid; i < 1024; i += 512) {
                float4 v = W4[i];
                int r = i >> 4, c = (i & 15) * 4;
                Wsh[r][c] = v.x; Wsh[r][c + 1] = v.y; Wsh[r][c + 2] = v.z; Wsh[r][c + 3] = v.w;
            }
            int beg = rp[d], end = rp[d + 1];
            float sdv = sd[d];
            float m = -1e30f;
            for (int j = beg + l8; j < end; j += 8) {
                float t = ss[cs[j]] + sdv;
                t = t > 0.f ? t : 0.2f * t;
                m = fmaxf(m, t);
            }
            m = fmaxf(m, __shfl_xor_sync(FULLMASK, m, 1));
            m = fmaxf(m, __shfl_xor_sync(FULLMASK, m, 2));
            m = fmaxf(m, __shfl_xor_sync(FULLMASK, m, 4));
            float s = 0.f;
            float4 a0 = {0,0,0,0}, a1 = {0,0,0,0}, a2 = {0,0,0,0}, a3 = {0,0,0,0};
            const float4* H4 = (const float4*)X;
            #pragma unroll 2
            for (int j = beg + sg; j < end; j += 2) {
                int src = cs[j];
                float t = ss[src] + sdv;
                t = t > 0.f ? t : 0.2f * t;
                float ex = __expf(t - m);
                s += ex;
                size_t hb = (size_t)src * 16 + gl * 4;
                float4 h0 = H4[hb], h1 = H4[hb + 1], h2 = H4[hb + 2], h3 = H4[hb + 3];
                a0.x = fmaf(ex, h0.x, a0.x); a0.y = fmaf(ex, h0.y, a0.y);
                a0.z = fmaf(ex, h0.z, a0.z); a0.w = fmaf(ex, h0.w, a0.w);
                a1.x = fmaf(ex, h1.x, a1.x); a1.y = fmaf(ex, h1.y, a1.y);
                a1.z = fmaf(ex, h1.z, a1.z); a1.w = fmaf(ex, h1.w, a1.w);
                a2.x = fmaf(ex, h2.x, a2.x); a2.y = fmaf(ex, h2.y, a2.y);
                a2.z = fmaf(ex, h2.z, a2.z); a2.w = fmaf(ex, h2.w, a2.w);
                a3.x = fmaf(ex, h3.x, a3.x); a3.y = fmaf(ex, h3.y, a3.y);
                a3.z = fmaf(ex, h3.z, a3.z); a3.w = fmaf(ex, h3.w, a3.w);
            }
            s += __shfl_xor_sync(FULLMASK, s, 4);
            a0.x += __shfl_xor_sync(FULLMASK, a0.x, 4); a0.y += __shfl_xor_sync(FULLMASK, a0.y, 4);
            a0.z += __shfl_xor_sync(FULLMASK, a0.z, 4); a0.w += __shfl_xor_sync(FULLMASK, a0.w, 4);
            a1.x += __shfl_xor_sync(FULLMASK, a1.x, 4); a1.y += __shfl_xor_sync(FULLMASK, a1.y, 4);
            a1.z += __shfl_xor_sync(FULLMASK, a1.z, 4); a1.w += __shfl_xor_sync(FULLMASK, a1.w, 4);
            a2.x += __shfl_xor_sync(FULLMASK, a2.x, 4); a2.y += __shfl_xor_sync(FULLMASK, a2.y, 4);
            a2.z += __shfl_xor_sync(FULLMASK, a2.z, 4); a2.w += __shfl_xor_sync(FULLMASK, a2.w, 4);
            a3.x += __shfl_xor_sync(FULLMASK, a3.x, 4); a3.y += __shfl_xor_sync(FULLMASK, a3.y, 4);
            a3.z += __shfl_xor_sync(FULLMASK, a3.z, 4); a3.w += __shfl_xor_sync(FULLMASK, a3.w, 4);
            float inv = s > 0.f ? 1.f / s : 0.f;
            if (sg == 0) {
                float4* Zr = (float4*)&Zs[g8 * 68];
                Zr[gl * 4]     = make_float4(a0.x * inv, a0.y * inv, a0.z * inv, a0.w * inv);
                Zr[gl * 4 + 1] = make_float4(a1.x * inv, a1.y * inv, a1.z * inv, a1.w * inv);
                Zr[gl * 4 + 2] = make_float4(a2.x * inv, a2.y * inv, a2.z * inv, a2.w * inv);
                Zr[gl * 4 + 3] = make_float4(a3.x * inv, a3.y * inv, a3.z * inv, a3.w * inv);
            }
            __syncthreads();
            #pragma unroll
            for (int k = 0; k < 64; k++) {
                float4 wv = *(const float4*)&Wsh[k][c0];
                float x0 = Zs[r0 * 68 + k], x1 = Zs[(r0 + 1) * 68 + k];
                acc[0][0] = fmaf(x0, wv.x, acc[0][0]); acc[0][1] = fmaf(x0, wv.y, acc[0][1]);
                acc[0][2] = fmaf(x0, wv.z, acc[0][2]); acc[0][3] = fmaf(x0, wv.w, acc[0][3]);
                acc[1][0] = fmaf(x1, wv.x, acc[1][0]); acc[1][1] = fmaf(x1, wv.y, acc[1][1]);
                acc[1][2] = fmaf(x1, wv.z, acc[1][2]); acc[1][3] = fmaf(x1, wv.w, acc[1][3]);
            }
            __syncthreads();
        }
        // bias + relu, stage to Zs
        #pragma unroll
        for (int i = 0; i < 2; i++)
            #pragma unroll
            for (int c = 0; c < 4; c++) {
                float v = acc[i][c] + b1[c0 + c] + b2[c0 + c];
                if (relu) v = fmaxf(v, 0.f);
                Zs[(r0 + i) * 68 + c0 + c] = v;
            }
        __syncthreads();
        float4 ot[2];
        const float4* Zr = (const float4*)&Zs[g8 * 68];
        ot[0] = Zr[l8 * 2]; ot[1] = Zr[l8 * 2 + 1];
        float4* Yr = (float4*)&Yp[(size_t)d * 64];
        Yr[l8 * 2] = ot[0]; Yr[l8 * 2 + 1] = ot[1];
#define PDOT(v, o) if (v) { \
        const float4* V4 = (const float4*)v; \
        float4 vv0 = V4[l8 * 2], vv1 = V4[l8 * 2 + 1]; \
        float dd = ot[0].x * vv0.x + ot[0].y * vv0.y + ot[0].z * vv0.z + ot[0].w * vv0.w \
                 + ot[1].x * vv1.x + ot[1].y * vv1.y + ot[1].z * vv1.z + ot[1].w * vv1.w; \
        dd += __shfl_xor_sync(FULLMASK, dd, 1); \
        dd += __shfl_xor_sync(FULLMASK, dd, 2); \
        dd += __shfl_xor_sync(FULLMASK, dd, 4); \
        if (l8 == 0) o[d] = dd; }
        PDOT(pv0, po0)
        PDOT(pv1, po1)
        PDOT(pv2, po2)
        PDOT(pv3, po3)
#undef PDOT
        // ---- hs epilogue: hs(l+1) = new_xp @ Wnext (Zs holds post-act xp rows) ----
        if (Wn0) {
            for (int p = 0; p < 2; p++) {
                const float* Wn = p ? Wn1 : Wn0;
                float* hsO = p ? hsOut1 : hsOut0;
                const float4* Wn4 = (const float4*)Wn;
                __syncthreads();
                for (int i = tid; i < 1024; i += 512) {
                    float4 v = Wn4[i];
                    int r = i >> 4, c = (i & 15) * 4;
                    Wsh[r][c] = v.x; Wsh[r][c + 1] = v.y; Wsh[r][c + 2] = v.z; Wsh[r][c + 3] = v.w;
                }
                __syncthreads();
                float ea[2][4] = {};
                #pragma unroll
                for (int k = 0; k < 64; k++) {
                    float4 wv = *(const float4*)&Wsh[k][c0];
                    float x0 = Zs[r0 * 68 + k], x1 = Zs[(r0 + 1) * 68 + k];
                    ea[0][0] = fmaf(x0, wv.x, ea[0][0]); ea[0][1] = fmaf(x0, wv.y, ea[0][1]);
                    ea[0][2] = fmaf(x0, wv.z, ea[0][2]); ea[0][3] = fmaf(x0, wv.w, ea[0][3]);
                    ea[1][0] = fmaf(x1, wv.x, ea[1][0]); ea[1][1] = fmaf(x1, wv.y, ea[1][1]);
                    ea[1][2] = fmaf(x1, wv.z, ea[1][2]); ea[1][3] = fmaf(x1, wv.w, ea[1][3]);
                }
                #pragma unroll
                for (int i = 0; i < 2; i++)
                    *(float4*)&hsO[((size_t)(row0 + r0 + i)) * 64 + c0] =
                        make_float4(ea[i][0], ea[i][1], ea[i][2], ea[i][3]);
            }
        }
    } else {
        // ---------------- tf-part: 4 lanes/row, two-pass fixed-max ----------------
        int tfIdx = blockIdx.x - npBlocks;
        bool isA = tfIdx < ntfA;
        int row0 = (isA ? tfIdx : tfIdx - ntfA) * 128;
        const int* rp = isA ? rpA : rpB;
        const int* cs = isA ? csA : csB;
        const float* ss = isA ? ssA : ssB;
        const float* sd = isA ? sdA : sdB;
        const float* hs = isA ? hsA : hsB;
        const float* b = isA ? bA : bB;
        float* Y = isA ? YA : YB;
        const float* v0 = isA ? vA0 : vB0;  float* o0 = isA ? oA0 : oB0;
        const float* v1 = isA ? vA1 : vB1;  float* o1 = isA ? oA1 : oB1;

        int g = tid >> 2, gl = tid & 3;
        int d = row0 + g;
        int beg = rp[d], end = rp[d + 1];
        float sdv = sd[d];
        float m = -1e30f;
        for (int j = beg + gl; j < end; j += 4) {
            float t = ss[cs[j]] + sdv;
            t = t > 0.f ? t : 0.2f * t;
            m = fmaxf(m, t);
        }
        m = fmaxf(m, __shfl_xor_sync(FULLMASK, m, 1));
        m = fmaxf(m, __shfl_xor_sync(FULLMASK, m, 2));
        float s = 0.f;
        float4 a0 = {0,0,0,0}, a1 = {0,0,0,0}, a2 = {0,0,0,0}, a3 = {0,0,0,0};
        const float4* H4 = (const float4*)hs;
        #pragma unroll 2
        for (int j = beg; j < end; j++) {
            int src = cs[j];
            float t = ss[src] + sdv;
            t = t > 0.f ? t : 0.2f * t;
            float ex = __expf(t - m);
            s += ex;
            size_t hb = (size_t)src * 16 + gl * 4;
            float4 h0 = H4[hb], h1 = H4[hb + 1], h2 = H4[hb + 2], h3 = H4[hb + 3];
            a0.x = fmaf(ex, h0.x, a0.x); a0.y = fmaf(ex, h0.y, a0.y);
            a0.z = fmaf(ex, h0.z, a0.z); a0.w = fmaf(ex, h0.w, a0.w);
            a1.x = fmaf(ex, h1.x, a1.x); a1.y = fmaf(ex, h1.y, a1.y);
            a1.z = fmaf(ex, h1.z, a1.z); a1.w = fmaf(ex, h1.w, a1.w);
            a2.x = fmaf(ex, h2.x, a2.x); a2.y = fmaf(ex, h2.y, a2.y);
            a2.z = fmaf(ex, h2.z, a2.z); a2.w = fmaf(ex, h2.w, a2.w);
            a3.x = fmaf(ex, h3.x, a3.x); a3.y = fmaf(ex, h3.y, a3.y);
            a3.z = fmaf(ex, h3.z, a3.z); a3.w = fmaf(ex, h3.w, a3.w);
        }
        float inv = s > 0.f ? 1.f / s : 0.f;
        const float4* B4 = (const float4*)b;
        float4 bb0 = B4[gl * 4], bb1 = B4[gl * 4 + 1], bb2 = B4[gl * 4 + 2], bb3 = B4[gl * 4 + 3];
        float4 ot[4];
        ot[0] = make_float4(a0.x * inv + bb0.x, a0.y * inv + bb0.y, a0.z * inv + bb0.z, a0.w * inv + bb0.w);
        ot[1] = make_float4(a1.x * inv + bb1.x, a1.y * inv + bb1.y, a1.z * inv + bb1.z, a1.w * inv + bb1.w);
        ot[2] = make_float4(a2.x * inv + bb2.x, a2.y * inv + bb2.y, a2.z * inv + bb2.z, a2.w * inv + bb2.w);
        ot[3] = make_float4(a3.x * inv + bb3.x, a3.y * inv + bb3.y, a3.z * inv + bb3.z, a3.w * inv + bb3.w);
        if (relu) {
            #pragma unroll
            for (int q = 0; q < 4; q++) {
                ot[q].x = fmaxf(ot[q].x, 0.f); ot[q].y = fmaxf(ot[q].y, 0.f);
                ot[q].z = fmaxf(ot[q].z, 0.f); ot[q].w = fmaxf(ot[q].w, 0.f);
            }
        }
        float4* Yr = (float4*)&Y[(size_t)d * 64];
        #pragma unroll
        for (int q = 0; q < 4; q++) Yr[gl * 4 + q] = ot[q];
#define TDOT(v, o) { \
        const float4* V4 = (const float4*)v; \
        float dd = 0.f; \
        _Pragma("unroll") \
        for (int q = 0; q < 4; q++) { \
            float4 vv = V4[gl * 4 + q]; \
            dd += ot[q].x * vv.x + ot[q].y * vv.y + ot[q].z * vv.z + ot[q].w * vv.w; \
        } \
        dd += __shfl_xor_sync(FULLMASK, dd, 1); \
        dd += __shfl_xor_sync(FULLMASK, dd, 2); \
        if (gl == 0) o[d] = dd; }
        TDOT(v0, o0)
        TDOT(v1, o1)
#undef TDOT
    }
}

// ---------------- pooling ----------------
__global__ void pool_k(const float* __restrict__ x, int npg, float* __restrict__ rep, int off) {
    int b = blockIdx.x;
    int t = threadIdx.x;            // 256
    int d = t & 63, c = t >> 6;
    const float* base = x + (size_t)b * npg * 64;
    float mx = -1e30f, mn = 1e30f, sm = 0.f;
    for (int n = c; n < npg; n += 4) {
        float v = base[(size_t)n * 64 + d];
        mx = fmaxf(mx, v); mn = fminf(mn, v); sm += v;
    }
    __shared__ float smx[4][64], smn[4][64], ssm[4][64];
    smx[c][d] = mx; smn[c][d] = mn; ssm[c][d] = sm;
    __syncthreads();
    if (c == 0) {
        for (int i = 1; i < 4; i++) {
            mx = fmaxf(mx, smx[i][d]); mn = fminf(mn, smn[i][d]); sm += ssm[i][d];
        }
        rep[b * 576 + off + d] = mx;
        rep[b * 576 + off + 64 + d] = mn;
        rep[b * 576 + off + 128 + d] = sm / (float)npg;
    }
}

// ---------------- LayerNorm + out_a projection ----------------
__global__ void ln_ra(const float* __restrict__ ap, const float* __restrict__ g,
                      const float* __restrict__ be, const float* __restrict__ Wa,
                      const float* __restrict__ ba, float* __restrict__ ra) {
    int idx = blockIdx.x * blockDim.x + threadIdx.x;
    int n = idx >> 5;
    if (n >= NPC) return;
    int lane = idx & 31;
    float2 v = *(const float2*)&ap[(size_t)n * 64 + lane * 2];
    float sum = v.x + v.y;
    for (int o = 16; o; o >>= 1) sum += __shfl_xor_sync(FULLMASK, sum, o);
    float mu = sum * (1.f / 64.f);
    float dx = v.x - mu, dy = v.y - mu;
    float vs = dx * dx + dy * dy;
    for (int o = 16; o; o >>= 1) vs += __shfl_xor_sync(FULLMASK, vs, o);
    float rs = rsqrtf(vs * (1.f / 64.f) + 1e-5f);
    float y0 = dx * rs * g[2 * lane] + be[2 * lane];
    float y1 = dy * rs * g[2 * lane + 1] + be[2 * lane + 1];
    float r0 = y0 * Wa[(2 * lane) * 2]     + y1 * Wa[(2 * lane + 1) * 2];
    float r1 = y0 * Wa[(2 * lane) * 2 + 1] + y1 * Wa[(2 * lane + 1) * 2 + 1];
    for (int o = 16; o; o >>= 1) r0 += __shfl_xor_sync(FULLMASK, r0, o);
    for (int o = 16; o; o >>= 1) r1 += __shfl_xor_sync(FULLMASK, r1, o);
    if (lane == 0) {
        ra[2 * n]     = r0 + ba[0];
        ra[2 * n + 1] = r1 + ba[1];
    }
}

// ---------------- per-graph softmax + scatter to actions ----------------
__device__ __forceinline__ float blk64_max(float v, volatile float* sh) {
    for (int o = 16; o; o >>= 1) v = fmaxf(v, __shfl_xor_sync(FULLMASK, v, o));
    if ((threadIdx.x & 31) == 0) sh[threadIdx.x >> 5] = v;
    __syncthreads();
    float r = fmaxf(sh[0], sh[1]);
    __syncthreads();
    return r;
}
__device__ __forceinline__ float blk64_sum(float v, volatile float* sh) {
    for (int o = 16; o; o >>= 1) v += __shfl_xor_sync(FULLMASK, v, o);
    if ((threadIdx.x & 31) == 0) sh[threadIdx.x >> 5] = v;
    __syncthreads();
    float r = sh[0] + sh[1];
    __syncthreads();
    return r;
}

__global__ void act_softmax(const float* __restrict__ ra, const int* __restrict__ part_id,
                            float* __restrict__ out) {
    __shared__ float sh[2];
    int b = blockIdx.x, t = threadIdx.x;        // 64
    int n = b * 64 + t;
    float v0 = ra[2 * n], v1 = ra[2 * n + 1];
    float m0 = blk64_max(v0, sh);
    float m1 = blk64_max(v1, sh);
    float e0 = expf(v0 - m0), e1 = expf(v1 - m1);
    float s0 = blk64_sum(e0, sh);
    float s1 = blk64_sum(e1, sh);
    int p = part_id[n];
    out[b * 128 + p] = e0 / s0;
    out[b * 128 + 64 + p] = e1 / s1;
}

// ---------------- value head MLPs ----------------
__global__ void mlp_k(const float* __restrict__ in, int K, const float* __restrict__ W,
                      const float* __restrict__ bias, float* __restrict__ out) {
    __shared__ float s[576];
    int b = blockIdx.x, j = threadIdx.x;        // 64
    for (int k = j; k < K; k += 64) s[k] = in[b * K + k];
    __syncthreads();
    float acc = bias[j];
    for (int k = 0; k < K; k++) acc = fmaf(s[k], W[k * 64 + j], acc);
    acc = 0.5f * acc * (1.f + erff(acc * 0.70710678118654752f));
    out[b * 64 + j] = acc;
}

__global__ void mlp_out(const float* __restrict__ h, const float* __restrict__ Wo,
                        const float* __restrict__ bo, float* __restrict__ V) {
    int idx = blockIdx.x * blockDim.x + threadIdx.x;
    int b = idx >> 5;
    if (b >= BC) return;
    int lane = idx & 31;
    float2 v = *(const float2*)&h[b * 64 + lane * 2];
    float s = v.x * Wo[2 * lane] + v.y * Wo[2 * lane + 1];
    for (int o = 16; o; o >>= 1) s += __shfl_xor_sync(FULLMASK, s, o);
    if (lane == 0) V[b] = tanhf(s + bo[0]);
}

// ---------------- host ----------------
#define SYMF(p, s) do { void* _q; cudaGetSymbolAddress(&_q, s); p = (float*)_q; } while (0)
#define SYMI(p, s) do { void* _q; cudaGetSymbolAddress(&_q, s); p = (int*)_q; } while (0)

extern "C" void kernel_launch(void* const* d_in, const int* in_sizes, int n_in,
                              void* d_out, int out_size) {
    const float* mass      = (const float*)d_in[0];
    const int*   pstate    = (const int*)d_in[1];
    const float* torque_x  = (const float*)d_in[2];
    const float* force_x   = (const float*)d_in[3];
    const int* e_pt_src = (const int*)d_in[4];
    const int* e_pt_dst = (const int*)d_in[5];
    const int* e_tp_src = (const int*)d_in[6];
    const int* e_tp_dst = (const int*)d_in[7];
    const int* e_pf_src = (const int*)d_in[8];
    const int* e_pf_dst = (const int*)d_in[9];
    const int* e_fp_src = (const int*)d_in[10];
    const int* e_fp_dst = (const int*)d_in[11];
    const int* part_id  = (const int*)d_in[13];
    const float* embW   = (const float*)d_in[14];
    const float* embS   = (const float*)d_in[15];
    const float* W_src  = (const float*)d_in[16];
    const float* W_dst  = (const float*)d_in[17];
    const float* a_src  = (const float*)d_in[18];
    const float* a_dst  = (const float*)d_in[19];
    const float* b_conv = (const float*)d_in[20];
    const float* ln_g   = (const float*)d_in[21];
    const float* ln_b   = (const float*)d_in[22];
    const float* outaW  = (const float*)d_in[23];
    const float* outab  = (const float*)d_in[24];
    const float* innW   = (const float*)d_in[25];
    const float* innb   = (const float*)d_in[26];
    const float* fulW   = (const float*)d_in[27];
    const float* fulb   = (const float*)d_in[28];
    const float* outW   = (const float*)d_in[29];
    const float* outb   = (const float*)d_in[30];
    float* out = (float*)d_out;

    float *xp, *xt, *xf, *ap, *hs0, *hs1;
    float *ss_pt, *ss_pf, *sd_tp, *sd_fp, *ss_tp, *sd_pt, *ss_fp, *sd_pf;
    float *wsv, *wdv, *ra, *rep, *h1, *h2;
    int *rp_pt, *rp_pf, *rp_tp, *rp_fp, *cs_pt, *cs_tp, *cs_pf, *cs_fp, *cnt, *aux;
    SYMF(xp, g_xp); SYMF(xt, g_xt); SYMF(xf, g_xf); SYMF(ap, g_ap);
    SYMF(hs0, g_hs0); SYMF(hs1, g_hs1);
    SYMF(ss_pt, g_ss_pt); SYMF(ss_pf, g_ss_pf); SYMF(sd_tp, g_sd_tp); SYMF(sd_fp, g_sd_fp);
    SYMF(ss_tp, g_ss_tp); SYMF(sd_pt, g_sd_pt); SYMF(ss_fp, g_ss_fp); SYMF(sd_pf, g_sd_pf);
    SYMF(wsv, g_wsv); SYMF(wdv, g_wdv); SYMF(ra, g_ra);
    SYMF(rep, g_rep); SYMF(h1, g_h1); SYMF(h2, g_h2);
    SYMI(rp_pt, g_rp_pt); SYMI(rp_pf, g_rp_pf); SYMI(rp_tp, g_rp_tp); SYMI(rp_fp, g_rp_fp);
    SYMI(cs_pt, g_cs_pt); SYMI(cs_tp, g_cs_tp); SYMI(cs_pf, g_cs_pf); SYMI(cs_fp, g_cs_fp);
    SYMI(cnt, g_cnt); SYMI(aux, g_aux);

    // batched CSR build (parallel 3-phase scan)
    zero4<<<(4 * NTC) / 256, 256>>>(cnt);
    { dim3 g(EC / 256, 4); hist4<<<g, 256>>>(e_pt_dst, e_tp_dst, e_pf_dst, e_fp_dst, cnt); }
    { dim3 g(128, 4); scanA<<<g, 1024>>>(cnt, rp_pt, rp_tp, rp_pf, rp_fp, aux); }
    scanB<<<1, 512>>>(aux);
    { dim3 g(128, 4); scanC<<<g, 1024>>>(cnt, rp_pt, rp_tp, rp_pf, rp_fp, aux); }
    { dim3 g(EC / 256, 4);
      scatter4<<<g, 256>>>(e_pt_src, e_pt_dst, e_tp_src, e_tp_dst,
                           e_pf_src, e_pf_dst, e_fp_src, e_fp_dst,
                           rp_pt, rp_tp, rp_pf, rp_fp, cnt,
                           cs_pt, cs_tp, cs_pf, cs_fp); }

    // score vectors; embed; layer-0 score dots (buffer 0); bootstrap hs (parity 0)
    vec_all<<<10, 256>>>(W_src, a_src, W_dst, a_dst, wsv, wdv);
    dot4<<<(NTC * 32) / 256, 256>>>(torque_x, NTC,
         wsv + 1 * 64, ss_tp, wdv + 0 * 64, sd_pt, nullptr, nullptr, nullptr, nullptr);
    dot4<<<(NFC * 32) / 256, 256>>>(force_x, NFC,
         wsv + 3 * 64, ss_fp, wdv + 2 * 64, sd_pf, nullptr, nullptr, nullptr, nullptr);
    embed_k<<<(NPC * 64) / 256, 256>>>(mass, pstate, embW, embS, xp);
    dot4<<<(NPC * 32) / 256, 256>>>(xp, NPC,
         wsv + 0 * 64, ss_pt, wsv + 2 * 64, ss_pf,
         wdv + 1 * 64, sd_tp, wdv + 3 * 64, sd_fp);
    mm_hs<<<2 * (NPC / 64), 256>>>(xp, W_src + 0 * 4096, hs0, W_src + 2 * 4096, hs1);

    for (int l = 0; l < 5; l++) {
        int ci = l & 1, ni = (l + 1) & 1;
        const float* xti = (l == 0) ? torque_x : xt + (size_t)ni * NTC * 64;
        const float* xfi = (l == 0) ? force_x  : xf + (size_t)ni * NFC * 64;
        float* xto = xt + (size_t)ci * NTC * 64;
        float* xfo = xf + (size_t)ci * NFC * 64;
        const float* Wl = W_src + (size_t)l * 4 * 4096;
        const float* bl = b_conv + (size_t)l * 4 * 64;
        int relu = (l < 3) ? 1 : 0;
        int actor = (l == 4);
        const float* nwsv = wsv + (size_t)(l + 1) * 4 * 64;
        const float* nwdv = wdv + (size_t)(l + 1) * 4 * 64;
        const float* c_ss_pt = ss_pt + ci * NPC;  float* n_ss_pt = ss_pt + ni * NPC;
        const float* c_ss_pf = ss_pf + ci * NPC;  float* n_ss_pf = ss_pf + ni * NPC;
        const float* c_sd_tp = sd_tp + ci * NPC;  float* n_sd_tp = sd_tp + ni * NPC;
        const float* c_sd_fp = sd_fp + ci * NPC;  float* n_sd_fp = sd_fp + ni * NPC;
        const float* c_ss_tp = ss_tp + ci * NTC;  float* n_ss_tp = ss_tp + ni * NTC;
        const float* c_sd_pt = sd_pt + ci * NTC;  float* n_sd_pt = sd_pt + ni * NTC;
        const float* c_ss_fp = ss_fp + ci * NFC;  float* n_ss_fp = ss_fp + ni * NFC;
        const float* c_sd_pf = sd_pf + ci * NFC;  float* n_sd_pf = sd_pf + ni * NFC;
        const float* hs0c = hs0 + (size_t)ci * NPC * 64;
        const float* hs1c = hs1 + (size_t)ci * NPC * 64;
        float* hs0n = hs0 + (size_t)ni * NPC * 64;
        float* hs1n = hs1 + (size_t)ni * NPC * 64;
        const float* Wnext = W_src + (size_t)(l + 1) * 4 * 4096;
        int doEpi = (l < 3);    // l=3's next layer (actor) needs no hs

        if (!actor) {
            mega<<<NPC / 64 + NTC / 128 + NFC / 128, 512>>>(
                NPC / 64, NTC / 128,
                rp_tp, cs_tp, c_ss_tp, c_sd_tp, xti, Wl + 1 * 4096,
                rp_fp, cs_fp, c_ss_fp, c_sd_fp, xfi, Wl + 3 * 4096,
                bl + 1 * 64, bl + 3 * 64, xp, relu,
                nwsv + 0 * 64, n_ss_pt, nwsv + 2 * 64, n_ss_pf,
                nwdv + 1 * 64, n_sd_tp, nwdv + 3 * 64, n_sd_fp,
                doEpi ? (Wnext + 0 * 4096) : nullptr, hs0n,
                doEpi ? (Wnext + 2 * 4096) : nullptr, hs1n,
                rp_pt, cs_pt, c_ss_pt, c_sd_pt, hs0c, bl + 0 * 64, xto,
                nwsv + 1 * 64, n_ss_tp, nwdv + 0 * 64, n_sd_pt,
                rp_pf, cs_pf, c_ss_pf, c_sd_pf, hs1c, bl + 2 * 64, xfo,
                nwsv + 3 * 64, n_ss_fp, nwdv + 2 * 64, n_sd_pf);
        } else {
            mega<<<NPC / 64, 512>>>(
                NPC / 64, 0,
                rp_tp, cs_tp, c_ss_tp, c_sd_tp, xti, Wl + 1 * 4096,
                rp_fp, cs_fp, c_ss_fp, c_sd_fp, xfi, Wl + 3 * 4096,
                bl + 1 * 64, bl + 3 * 64, ap, 0,
                nullptr, nullptr, nullptr, nullptr,
                nullptr, nullptr, nullptr, nullptr,
                nullptr, nullptr, nullptr, nullptr,
                nullptr, nullptr, nullptr, nullptr, nullptr, nullptr, nullptr,
                nullptr, nullptr, nullptr, nullptr,
                nullptr, nullptr, nullptr, nullptr, nullptr, nullptr, nullptr,
                nullptr, nullptr, nullptr, nullptr);
        }
    }

    // pooling over final x: l=3 wrote xt/xf parity 1; xp in place
    pool_k<<<BC, 256>>>(xp, 64, rep, 0);
    pool_k<<<BC, 256>>>(xt + (size_t)NTC * 64, 512, rep, 192);
    pool_k<<<BC, 256>>>(xf + (size_t)NFC * 64, 512, rep, 384);

    // actor head
    ln_ra<<<(NPC * 32) / 256, 256>>>(ap, ln_g, ln_b, outaW, outab, ra);
    act_softmax<<<BC, 64>>>(ra, part_id, out);

    // value head
    mlp_k<<<BC, 64>>>(rep, 576, innW, innb, h1);
    mlp_k<<<BC, 64>>>(h1, 64, fulW, fulb, h2);
    mlp_out<<<(BC * 32) / 256, 256>>>(h2, outW, outb, out + BC * 128);
}